// round 8
// baseline (speedup 1.0000x reference)
#include <cuda_runtime.h>
#include <cuda_bf16.h>
#include <math.h>
#include <stdint.h>

#define Rr   10000
#define E    256
#define Bb   1024
#define L    8
#define RP1  10001
#define KPAD 10240            // padded K for probsf@emb_w (mult of 32)
#define NPADW 10112           // fc2_w rows padded to 79*128
#define SPLITK 10
#define KSPL 1024             // KPAD / SPLITK

// packed f32x2 helpers (Blackwell FFMA2)
#define PACKF2(d, lo, hi) asm("mov.b64 %0, {%1, %2};" : "=l"(d) : "f"(lo), "f"(hi))
#define FMAF2(acc, a, b)  asm("fma.rn.f32x2 %0, %1, %2, %0;" : "+l"(acc) : "l"(a), "l"(b))
#define UNPACKF2(lo, hi, v) asm("mov.b64 {%0, %1}, %2;" : "=f"(lo), "=f"(hi) : "l"(v))

// ---------------- scratch ----------------
__device__ float g_xT[Bb*L*E];                    // [t*1024+b][E] fp32
__device__ __nv_bfloat16 g_xhi[Bb*L*E];
__device__ __nv_bfloat16 g_xlo[Bb*L*E];
__device__ float g_hid[Bb*L*E];                   // [b][t][E]
__device__ float g_h[Bb*E];
__device__ float g_h2[Bb*E];
__device__ float g_c[Bb*E];
__device__ float g_gx[(size_t)Bb*L*4*E];          // [t*1024+b][4E]
__device__ __nv_bfloat16 g_h1hi[Bb*E];
__device__ __nv_bfloat16 g_h1lo[Bb*E];
__device__ __nv_bfloat16 g_psfhi[(size_t)Bb*KPAD];
__device__ __nv_bfloat16 g_psflo[(size_t)Bb*KPAD];
__device__ float g_psflast[Bb];
__device__ __nv_bfloat16 g_embThi[(size_t)E*KPAD]; // [e][k] K-major
__device__ __nv_bfloat16 g_embTlo[(size_t)E*KPAD];
__device__ __nv_bfloat16 g_fc2whi[(size_t)NPADW*E];
__device__ __nv_bfloat16 g_fc2wlo[(size_t)NPADW*E];
__device__ __nv_bfloat16 g_wihhi[4*E*E];
__device__ __nv_bfloat16 g_wihlo[4*E*E];
__device__ float g_biassum[4*E];
__device__ float g_part[SPLITK*Bb*E];

// ---------------- ptx helpers ----------------
__device__ __forceinline__ uint32_t s2u(const void* p) {
    uint32_t a;
    asm("{ .reg .u64 t; cvta.to.shared.u64 t, %1; cvt.u32.u64 %0, t; }" : "=r"(a) : "l"(p));
    return a;
}
__device__ __forceinline__ void ldm4(uint32_t* r, uint32_t addr) {
    asm volatile("ldmatrix.sync.aligned.m8n8.x4.shared.b16 {%0,%1,%2,%3}, [%4];"
                 : "=r"(r[0]), "=r"(r[1]), "=r"(r[2]), "=r"(r[3]) : "r"(addr));
}
__device__ __forceinline__ void mma_bf16(float* d, const uint32_t* a, const uint32_t* b) {
    asm volatile("mma.sync.aligned.m16n8k16.row.col.f32.bf16.bf16.f32 "
                 "{%0,%1,%2,%3}, {%4,%5,%6,%7}, {%8,%9}, {%0,%1,%2,%3};"
                 : "+f"(d[0]), "+f"(d[1]), "+f"(d[2]), "+f"(d[3])
                 : "r"(a[0]), "r"(a[1]), "r"(a[2]), "r"(a[3]), "r"(b[0]), "r"(b[1]));
}
__device__ __forceinline__ void cpa16(uint32_t saddr, const void* gptr) {
    asm volatile("cp.async.cg.shared.global [%0], [%1], 16;" :: "r"(saddr), "l"(gptr) : "memory");
}
#define CP_COMMIT() asm volatile("cp.async.commit_group;" ::: "memory")
#define CP_WAIT1()  asm volatile("cp.async.wait_group 1;" ::: "memory")
#define CP_WAIT0()  asm volatile("cp.async.wait_group 0;" ::: "memory")

__device__ __forceinline__ void split_bf16(float x, __nv_bfloat16& h, __nv_bfloat16& l) {
    h = __float2bfloat16(x);
    l = __float2bfloat16(x - __bfloat162float(h));
}

// ---------------- double-buffered warp-MMA split-bf16 GEMM (unchanged from R7) ----------------
#define SSTR 40
#define STAGE_B 40960
#define HMMA_SMEM (2*STAGE_B)
__global__ void __launch_bounds__(256)
hmma_gemm(const __nv_bfloat16* __restrict__ Ahi, const __nv_bfloat16* __restrict__ Alo, int lda,
          const __nv_bfloat16* __restrict__ Bhi, const __nv_bfloat16* __restrict__ Blo, int ldb,
          float* __restrict__ C, int ldc, int Nreal, int Klen, size_t zstride,
          const float* __restrict__ bias)
{
    extern __shared__ char dsm[];
    const uint32_t sb = s2u(dsm);

    const int tid = threadIdx.x, lane = tid & 31, wid = tid >> 5;
    const int bm = blockIdx.y * 128, bn = blockIdx.x * 128;
    const int kbase = blockIdx.z * Klen;
    C += (size_t)blockIdx.z * zstride;
    const int wm = (wid & 1) * 64, wn = (wid >> 1) * 32;

    float acc[4][4][4];
#pragma unroll
    for (int i = 0; i < 4; i++)
#pragma unroll
        for (int j = 0; j < 4; j++)
#pragma unroll
            for (int u = 0; u < 4; u++) acc[i][j][u] = 0.f;

    const int l15 = lane & 15, lq = lane >> 4;
    const int l8 = lane & 7, sel = lane >> 3;
    const int row0 = tid >> 2, q0 = tid & 3;
    const int row1 = row0 + 64, q1 = q0;
    const int ntiles = Klen >> 5;

    {
        size_t ga0 = (size_t)(bm + row0) * lda + kbase + q0 * 8;
        size_t gb0 = (size_t)(bn + row0) * ldb + kbase + q0 * 8;
        size_t ga1 = (size_t)(bm + row1) * lda + kbase + q1 * 8;
        size_t gb1 = (size_t)(bn + row1) * ldb + kbase + q1 * 8;
        uint32_t s0 = sb + (uint32_t)(row0 * SSTR + q0 * 8) * 2;
        uint32_t s1 = sb + (uint32_t)(row1 * SSTR + q1 * 8) * 2;
        cpa16(s0,         Ahi + ga0); cpa16(s0 + 10240, Alo + ga0);
        cpa16(s0 + 20480, Bhi + gb0); cpa16(s0 + 30720, Blo + gb0);
        cpa16(s1,         Ahi + ga1); cpa16(s1 + 10240, Alo + ga1);
        cpa16(s1 + 20480, Bhi + gb1); cpa16(s1 + 30720, Blo + gb1);
        CP_COMMIT();
    }

    for (int t = 0; t < ntiles; t++) {
        if (t + 1 < ntiles) {
            int kt = kbase + (t + 1) * 32;
            uint32_t stb = sb + ((t + 1) & 1) * STAGE_B;
            size_t ga0 = (size_t)(bm + row0) * lda + kt + q0 * 8;
            size_t gb0 = (size_t)(bn + row0) * ldb + kt + q0 * 8;
            size_t ga1 = (size_t)(bm + row1) * lda + kt + q1 * 8;
            size_t gb1 = (size_t)(bn + row1) * ldb + kt + q1 * 8;
            uint32_t s0 = stb + (uint32_t)(row0 * SSTR + q0 * 8) * 2;
            uint32_t s1 = stb + (uint32_t)(row1 * SSTR + q1 * 8) * 2;
            cpa16(s0,         Ahi + ga0); cpa16(s0 + 10240, Alo + ga0);
            cpa16(s0 + 20480, Bhi + gb0); cpa16(s0 + 30720, Blo + gb0);
            cpa16(s1,         Ahi + ga1); cpa16(s1 + 10240, Alo + ga1);
            cpa16(s1 + 20480, Bhi + gb1); cpa16(s1 + 30720, Blo + gb1);
            CP_COMMIT();
            CP_WAIT1();
        } else {
            CP_WAIT0();
        }
        __syncthreads();

        const uint32_t stb = sb + (t & 1) * STAGE_B;
        const uint32_t aHi = stb, aLo = stb + 10240, bHi = stb + 20480, bLo = stb + 30720;

#pragma unroll
        for (int ks = 0; ks < 2; ks++) {
            uint32_t ahi[4][4], alo[4][4];
#pragma unroll
            for (int mf = 0; mf < 4; mf++) {
                uint32_t off = (uint32_t)((wm + mf * 16 + l15) * SSTR + ks * 16 + lq * 8) * 2;
                ldm4(ahi[mf], aHi + off);
                ldm4(alo[mf], aLo + off);
            }
            uint32_t bhi[4][2], blo[4][2];
#pragma unroll
            for (int p = 0; p < 2; p++) {
                uint32_t off = (uint32_t)((wn + p * 16 + (sel >> 1) * 8 + l8) * SSTR
                                          + ks * 16 + (sel & 1) * 8) * 2;
                uint32_t r[4];
                ldm4(r, bHi + off);
                bhi[p*2][0] = r[0]; bhi[p*2][1] = r[1];
                bhi[p*2+1][0] = r[2]; bhi[p*2+1][1] = r[3];
                ldm4(r, bLo + off);
                blo[p*2][0] = r[0]; blo[p*2][1] = r[1];
                blo[p*2+1][0] = r[2]; blo[p*2+1][1] = r[3];
            }
#pragma unroll
            for (int mf = 0; mf < 4; mf++)
#pragma unroll
                for (int nf = 0; nf < 4; nf++) {
                    mma_bf16(acc[mf][nf], ahi[mf], bhi[nf]);
                    mma_bf16(acc[mf][nf], ahi[mf], blo[nf]);
                    mma_bf16(acc[mf][nf], alo[mf], bhi[nf]);
                }
        }
        __syncthreads();
    }

    const int crow = lane >> 2, ccol = (lane & 3) * 2;
#pragma unroll
    for (int mf = 0; mf < 4; mf++) {
        int r0 = bm + wm + mf * 16 + crow;
#pragma unroll
        for (int nf = 0; nf < 4; nf++) {
            int c0 = bn + wn + nf * 8 + ccol;
#pragma unroll
            for (int half = 0; half < 2; half++) {
                int r = r0 + half * 8;
#pragma unroll
                for (int u = 0; u < 2; u++) {
                    int n = c0 + u;
                    if (n < Nreal) {
                        float v = acc[mf][nf][half * 2 + u];
                        if (bias) v += bias[n];
                        C[(size_t)r * ldc + n] = v;
                    }
                }
            }
        }
    }
}

// ---------------- fused LSTM step: gates GEMM + cell update ----------------
// grid (E/64, Bb/32) = (4, 32) = 128 blocks, 256 threads.
// Each block: batch rows b0..b0+31, e-cols e0..e0+63, all 4 gates.
__device__ __forceinline__ float sigm(float x) { return 1.f / (1.f + __expf(-x)); }

__global__ void __launch_bounds__(256)
lstm_step_kernel(const float* __restrict__ hsrc, float* __restrict__ hdst,
                 const float* __restrict__ w_hh, int t)
{
    __shared__ float As[16][36];       // [k][row]
    __shared__ float Bs[4][16][68];    // [gate][k][n]
    const int tid = threadIdx.x;
    const int e0 = blockIdx.x * 64, b0 = blockIdx.y * 32;
    const int tx = tid & 15, ty = tid >> 4;

    unsigned long long acc[4][2][2];
#pragma unroll
    for (int g = 0; g < 4; g++)
#pragma unroll
        for (int i = 0; i < 2; i++) { acc[g][i][0] = 0ULL; acc[g][i][1] = 0ULL; }

    for (int kt = 0; kt < E; kt += 16) {
#pragma unroll
        for (int jj = 0; jj < 2; jj++) {
            int ii = tid + jj * 256;
            int k = ii & 15, row = ii >> 4;
            As[k][row] = hsrc[(size_t)(b0 + row) * E + kt + k];
        }
#pragma unroll
        for (int jj = 0; jj < 4; jj++) {
            int ii = tid + jj * 256;
            int kq = ii & 3, n = (ii >> 2) & 63, g = ii >> 8;
            float4 v = *(const float4*)&w_hh[(size_t)(g * E + e0 + n) * E + kt + kq * 4];
            Bs[g][kq*4+0][n] = v.x; Bs[g][kq*4+1][n] = v.y;
            Bs[g][kq*4+2][n] = v.z; Bs[g][kq*4+3][n] = v.w;
        }
        __syncthreads();
#pragma unroll
        for (int kk = 0; kk < 16; kk++) {
            float a0 = As[kk][ty*2], a1 = As[kk][ty*2+1];
            unsigned long long a20, a21;
            PACKF2(a20, a0, a0); PACKF2(a21, a1, a1);
#pragma unroll
            for (int g = 0; g < 4; g++) {
                float4 b4 = *(const float4*)&Bs[g][kk][tx*4];
                unsigned long long bp0, bp1;
                PACKF2(bp0, b4.x, b4.y); PACKF2(bp1, b4.z, b4.w);
                FMAF2(acc[g][0][0], a20, bp0); FMAF2(acc[g][0][1], a20, bp1);
                FMAF2(acc[g][1][0], a21, bp0); FMAF2(acc[g][1][1], a21, bp1);
            }
        }
        __syncthreads();
    }

#pragma unroll
    for (int i = 0; i < 2; i++) {
        int b = b0 + ty * 2 + i;
        float ga[4][4];
#pragma unroll
        for (int g = 0; g < 4; g++) {
            float v0, v1, v2, v3;
            UNPACKF2(v0, v1, acc[g][i][0]);
            UNPACKF2(v2, v3, acc[g][i][1]);
            ga[g][0] = v0; ga[g][1] = v1; ga[g][2] = v2; ga[g][3] = v3;
        }
        const float* gxr = g_gx + ((size_t)t * Bb + b) * (4 * E);
#pragma unroll
        for (int j = 0; j < 4; j++) {
            int e = e0 + tx * 4 + j;
            float gi = ga[0][j] + gxr[e];
            float gf = ga[1][j] + gxr[E + e];
            float gg = ga[2][j] + gxr[2 * E + e];
            float go = ga[3][j] + gxr[3 * E + e];
            float co = g_c[b * E + e];
            float cc = sigm(gf) * co + sigm(gi) * tanhf(gg);
            float hh = sigm(go) * tanhf(cc);
            g_c[b * E + e] = cc;
            hdst[b * E + e] = hh;
            g_hid[b * (L * E) + t * E + e] = hh;
        }
    }
}

// ---------------- prep / elementwise kernels ----------------
__global__ void prep_bias_kernel(const float* __restrict__ b_ih, const float* __restrict__ b_hh) {
    int idx = blockIdx.x * 256 + threadIdx.x;
    if (idx < 4 * E) g_biassum[idx] = b_ih[idx] + b_hh[idx];
}

__global__ void conv_fc2w_kernel(const float* __restrict__ fc2_w) {
    int idx = blockIdx.x * 256 + threadIdx.x;
    int r = idx >> 8, c = idx & 255;
    float v = (r < RP1) ? fc2_w[r * E + c] : 0.f;
    split_bf16(v, g_fc2whi[idx], g_fc2wlo[idx]);
}

__global__ void conv_wih_kernel(const float* __restrict__ w_ih) {
    int idx = blockIdx.x * 256 + threadIdx.x;
    split_bf16(w_ih[idx], g_wihhi[idx], g_wihlo[idx]);
}

__global__ void conv_embT_kernel(const float* __restrict__ emb_w) {
    __shared__ float tile[32][33];
    int k0 = blockIdx.x * 32, e0 = blockIdx.y * 32;
    int tx = threadIdx.x & 31, ty = threadIdx.x >> 5;
#pragma unroll
    for (int r = 0; r < 32; r += 8) {
        int k = k0 + ty + r;
        tile[ty + r][tx] = (k < Rr) ? emb_w[(size_t)k * E + e0 + tx] : 0.f;
    }
    __syncthreads();
#pragma unroll
    for (int r = 0; r < 32; r += 8) {
        int e = e0 + ty + r;
        float v = tile[tx][ty + r];
        split_bf16(v, g_embThi[(size_t)e * KPAD + k0 + tx],
                      g_embTlo[(size_t)e * KPAD + k0 + tx]);
    }
}

__global__ void embed_kernel(const int* __restrict__ bodys, const float* __restrict__ emb_w) {
    int idx = blockIdx.x * 256 + threadIdx.x;
    int e = idx & 255, b = (idx >> 8) & 1023, t = idx >> 18;
    float v = emb_w[(size_t)bodys[b * L + t] * E + e];
    g_xT[idx] = v;
    split_bf16(v, g_xhi[idx], g_xlo[idx]);
    if (idx < Bb * E) { g_h[idx] = 0.f; g_c[idx] = 0.f; }
}

__global__ void concat0_kernel(float* __restrict__ out_emb) {
    int idx = blockIdx.x * 256 + threadIdx.x;
    int b = idx >> 9, j = idx & 511;
    out_emb[idx] = (j < E) ? g_xT[b * E + j] : g_xT[(1024 + b) * E + (j - E)];
}

__global__ void emb1_finish_kernel(float* __restrict__ out_emb,
                                   const float* __restrict__ emb_w, int i) {
    int idx = blockIdx.x * 256 + threadIdx.x;
    int b = idx >> 8, e = idx & 255;
    float s = 0.f;
#pragma unroll
    for (int p = 0; p < SPLITK; p++) s += g_part[p * (Bb * E) + idx];
    s += g_psflast[b] * g_hid[b * (L * E) + i * E + e];
    out_emb[b * (2 * E) + e]     = s;
    out_emb[b * (2 * E) + E + e] = emb_w[(i + 1) * E + e];
}

// online softmax: one fused max+sum pass, one write pass
__global__ void softmax_kernel(const float* __restrict__ prob) {
    int b = blockIdx.x;
    const float* row = prob + (size_t)b * RP1;
    __nv_bfloat16* ohi = g_psfhi + (size_t)b * KPAD;
    __nv_bfloat16* olo = g_psflo + (size_t)b * KPAD;
    __shared__ float rm[256], rs[256];
    int t = threadIdx.x;
    float m = -1e30f, s = 0.f;
    for (int j = t; j < RP1; j += 256) {
        float x = row[j];
        float mn = fmaxf(m, x);
        s = s * __expf(m - mn) + __expf(x - mn);
        m = mn;
    }
    rm[t] = m; rs[t] = s; __syncthreads();
    for (int st = 128; st > 0; st >>= 1) {
        if (t < st) {
            float m2 = rm[t + st], s2 = rs[t + st];
            float mn = fmaxf(rm[t], m2);
            rs[t] = rs[t] * __expf(rm[t] - mn) + s2 * __expf(m2 - mn);
            rm[t] = mn;
        }
        __syncthreads();
    }
    m = rm[0];
    float inv = 1.f / rs[0];
    for (int j = t; j < KPAD; j += 256) {
        if (j < Rr) {
            float v = __expf(row[j] - m) * inv;
            split_bf16(v, ohi[j], olo[j]);
        } else {
            if (j == Rr) g_psflast[b] = __expf(row[j] - m) * inv;
            ohi[j] = __float2bfloat16(0.f);
            olo[j] = __float2bfloat16(0.f);
        }
    }
}

// ---------------- 64x64 FFMA2 GEMM (fc1) with optional split-bf16 output ----------------
#define BMT 64
#define BNT 64
#define BKT 16
template<bool TRANSB, bool RELU>
__global__ void gemm_kernel(const float* __restrict__ A, int lda,
                            const float* __restrict__ B, int ldb,
                            float* __restrict__ C, int ldc,
                            int M, int N, int Klen,
                            const float* __restrict__ bias,
                            __nv_bfloat16* __restrict__ Ohi,
                            __nv_bfloat16* __restrict__ Olo)
{
    __shared__ float As[BKT][BMT + 4];
    __shared__ float Bs[BKT][BNT + 4];
    int bm = blockIdx.y * BMT, bn = blockIdx.x * BNT;
    int tid = threadIdx.x;
    int tx = tid & 15, ty = tid >> 4;
    unsigned long long acc[4][2];
#pragma unroll
    for (int i = 0; i < 4; i++) { acc[i][0] = 0ULL; acc[i][1] = 0ULL; }

    for (int kt = 0; kt < Klen; kt += BKT) {
#pragma unroll
        for (int j = 0; j < 4; j++) {
            int idx = tid + j * 256;
            int m = idx >> 4, k = idx & 15;
            As[k][m] = A[(size_t)(bm + m) * lda + kt + k];
        }
#pragma unroll
        for (int j = 0; j < 4; j++) {
            int idx = tid + j * 256;
            if (TRANSB) {
                int n = idx >> 4, k = idx & 15;
                Bs[k][n] = (bn + n < N) ? B[(size_t)(bn + n) * ldb + kt + k] : 0.f;
            } else {
                int k = idx >> 6, n = idx & 63;
                Bs[k][n] = (bn + n < N) ? B[(size_t)(kt + k) * ldb + bn + n] : 0.f;
            }
        }
        __syncthreads();
#pragma unroll
        for (int kk = 0; kk < BKT; kk++) {
            float4 a4 = *(const float4*)&As[kk][ty * 4];
            float4 b4 = *(const float4*)&Bs[kk][tx * 4];
            unsigned long long bp0, bp1;
            PACKF2(bp0, b4.x, b4.y); PACKF2(bp1, b4.z, b4.w);
            float av[4] = {a4.x, a4.y, a4.z, a4.w};
#pragma unroll
            for (int i = 0; i < 4; i++) {
                unsigned long long a2;
                PACKF2(a2, av[i], av[i]);
                FMAF2(acc[i][0], a2, bp0);
                FMAF2(acc[i][1], a2, bp1);
            }
        }
        __syncthreads();
    }
#pragma unroll
    for (int i = 0; i < 4; i++) {
        int m = bm + ty * 4 + i;
#pragma unroll
        for (int j = 0; j < 2; j++) {
            int nbase = bn + tx * 4 + 2 * j;
            float lo, hi;
            UNPACKF2(lo, hi, acc[i][j]);
#pragma unroll
            for (int u = 0; u < 2; u++) {
                int n = nbase + u;
                if (n < N) {
                    float v = (u == 0) ? lo : hi;
                    if (bias) v += bias[n];
                    if (RELU) v = fmaxf(v, 0.f);
                    if (Ohi) {
                        __nv_bfloat16 vh, vl;
                        split_bf16(v, vh, vl);
                        Ohi[(size_t)m * ldc + n] = vh;
                        Olo[(size_t)m * ldc + n] = vl;
                    } else {
                        C[(size_t)m * ldc + n] = v;
                    }
                }
            }
        }
    }
}

// ---------------- launch ----------------
extern "C" void kernel_launch(void* const* d_in, const int* in_sizes, int n_in,
                              void* d_out, int out_size) {
    const int*   bodys = (const int*)  d_in[0];
    const float* emb_w = (const float*)d_in[1];
    const float* w_ih  = (const float*)d_in[2];
    const float* w_hh  = (const float*)d_in[3];
    const float* b_ih  = (const float*)d_in[4];
    const float* b_hh  = (const float*)d_in[5];
    const float* fc1_w = (const float*)d_in[6];
    const float* fc1_b = (const float*)d_in[7];
    const float* fc2_w = (const float*)d_in[8];
    const float* fc2_b = (const float*)d_in[9];

    float* out_prob = (float*)d_out;
    float* out_emb  = out_prob + (size_t)Bb * RP1;

    cudaFuncSetAttribute(hmma_gemm, cudaFuncAttributeMaxDynamicSharedMemorySize, HMMA_SMEM);

    float *biassum, *part, *gx, *h, *h2;
    __nv_bfloat16 *xhi, *xlo, *h1hi, *h1lo, *psfhi, *psflo, *eThi, *eTlo, *f2hi, *f2lo, *wihhi, *wihlo;
    cudaGetSymbolAddress((void**)&biassum, g_biassum);
    cudaGetSymbolAddress((void**)&part,    g_part);
    cudaGetSymbolAddress((void**)&gx,      g_gx);
    cudaGetSymbolAddress((void**)&h,       g_h);
    cudaGetSymbolAddress((void**)&h2,      g_h2);
    cudaGetSymbolAddress((void**)&xhi,     g_xhi);
    cudaGetSymbolAddress((void**)&xlo,     g_xlo);
    cudaGetSymbolAddress((void**)&h1hi,    g_h1hi);
    cudaGetSymbolAddress((void**)&h1lo,    g_h1lo);
    cudaGetSymbolAddress((void**)&psfhi,   g_psfhi);
    cudaGetSymbolAddress((void**)&psflo,   g_psflo);
    cudaGetSymbolAddress((void**)&eThi,    g_embThi);
    cudaGetSymbolAddress((void**)&eTlo,    g_embTlo);
    cudaGetSymbolAddress((void**)&f2hi,    g_fc2whi);
    cudaGetSymbolAddress((void**)&f2lo,    g_fc2wlo);
    cudaGetSymbolAddress((void**)&wihhi,   g_wihhi);
    cudaGetSymbolAddress((void**)&wihlo,   g_wihlo);

    // launch order puts the gx HMMA in the profiler's capture slot (4th launch)
    prep_bias_kernel<<<4, 256>>>(b_ih, b_hh);
    conv_wih_kernel<<<(4 * E * E) / 256, 256>>>(w_ih);
    embed_kernel<<<8192, 256>>>(bodys, emb_w);
    hmma_gemm<<<dim3(8, 64), 256, HMMA_SMEM>>>(
        xhi, xlo, E, wihhi, wihlo, E,
        gx, 4 * E, 4 * E, E, 0, biassum);
    conv_fc2w_kernel<<<(NPADW * E) / 256, 256>>>(fc2_w);
    conv_embT_kernel<<<dim3(KPAD / 32, E / 32), 256>>>(emb_w);

    // fused LSTM steps, h double-buffered
    for (int t = 0; t < L; t++) {
        const float* hs = (t & 1) ? h2 : h;
        float* hd       = (t & 1) ? h  : h2;
        lstm_step_kernel<<<dim3(4, 32), 256>>>(hs, hd, w_hh, t);
    }

    for (int i = 0; i < L - 1; i++) {
        if (i == 0) {
            concat0_kernel<<<2048, 256>>>(out_emb);
        } else {
            hmma_gemm<<<dim3(2, 8, SPLITK), 256, HMMA_SMEM>>>(
                psfhi, psflo, KPAD, eThi, eTlo, KPAD,
                part, E, E, KSPL, (size_t)Bb * E, nullptr);
            emb1_finish_kernel<<<1024, 256>>>(out_emb, emb_w, i);
        }
        // hidden1 = relu(emb_concat @ fc1_w^T + fc1_b) -> split bf16 direct
        gemm_kernel<true, true><<<dim3(4, 16), 256>>>(
            out_emb, 2 * E, fc1_w, 2 * E, nullptr, E, Bb, E, 2 * E,
            fc1_b, h1hi, h1lo);
        // prob = hidden1 @ fc2_w^T + fc2_b
        hmma_gemm<<<dim3(79, 8), 256, HMMA_SMEM>>>(
            h1hi, h1lo, E, f2hi, f2lo, E,
            out_prob, RP1, RP1, E, 0, fc2_b);
        if (i < L - 2) softmax_kernel<<<1024, 256>>>(out_prob);
    }
}

// round 9
// speedup vs baseline: 1.0404x; 1.0404x over previous
#include <cuda_runtime.h>
#include <cuda_bf16.h>
#include <math.h>
#include <stdint.h>

#define Rr   10000
#define E    256
#define Bb   1024
#define L    8
#define RP1  10001
#define KPAD 10240            // padded K for probsf@emb_w (mult of 32)
#define NPADW 10112           // fc2_w rows padded to 79*128
#define SPLITK 10
#define KSPL 1024             // KPAD / SPLITK

// packed f32x2 helpers (Blackwell FFMA2)
#define PACKF2(d, lo, hi) asm("mov.b64 %0, {%1, %2};" : "=l"(d) : "f"(lo), "f"(hi))
#define FMAF2(acc, a, b)  asm("fma.rn.f32x2 %0, %1, %2, %0;" : "+l"(acc) : "l"(a), "l"(b))
#define UNPACKF2(lo, hi, v) asm("mov.b64 {%0, %1}, %2;" : "=f"(lo), "=f"(hi) : "l"(v))

// ---------------- scratch ----------------
__device__ float g_xT[Bb*L*E];                    // [t*1024+b][E] fp32
__device__ __nv_bfloat16 g_xhi[Bb*L*E];
__device__ __nv_bfloat16 g_xlo[Bb*L*E];
__device__ float g_hid[Bb*L*E];                   // [b][t][E]
__device__ float g_h[Bb*E];
__device__ float g_c[Bb*E];
__device__ float g_gates[Bb*4*E];
__device__ float g_gx[(size_t)Bb*L*4*E];          // [t*1024+b][4E]
__device__ __nv_bfloat16 g_h1hi[Bb*E];
__device__ __nv_bfloat16 g_h1lo[Bb*E];
__device__ __nv_bfloat16 g_psfhi[(size_t)Bb*KPAD];
__device__ __nv_bfloat16 g_psflo[(size_t)Bb*KPAD];
__device__ float g_psflast[Bb];
__device__ __nv_bfloat16 g_embThi[(size_t)E*KPAD]; // [e][k] K-major
__device__ __nv_bfloat16 g_embTlo[(size_t)E*KPAD];
__device__ __nv_bfloat16 g_fc2whi[(size_t)NPADW*E];
__device__ __nv_bfloat16 g_fc2wlo[(size_t)NPADW*E];
__device__ __nv_bfloat16 g_wihhi[4*E*E];
__device__ __nv_bfloat16 g_wihlo[4*E*E];
__device__ float g_biassum[4*E];
__device__ float g_part[SPLITK*Bb*E];

// ---------------- ptx helpers ----------------
__device__ __forceinline__ uint32_t s2u(const void* p) {
    uint32_t a;
    asm("{ .reg .u64 t; cvta.to.shared.u64 t, %1; cvt.u32.u64 %0, t; }" : "=r"(a) : "l"(p));
    return a;
}
__device__ __forceinline__ void ldm4(uint32_t* r, uint32_t addr) {
    asm volatile("ldmatrix.sync.aligned.m8n8.x4.shared.b16 {%0,%1,%2,%3}, [%4];"
                 : "=r"(r[0]), "=r"(r[1]), "=r"(r[2]), "=r"(r[3]) : "r"(addr));
}
__device__ __forceinline__ void mma_bf16(float* d, const uint32_t* a, const uint32_t* b) {
    asm volatile("mma.sync.aligned.m16n8k16.row.col.f32.bf16.bf16.f32 "
                 "{%0,%1,%2,%3}, {%4,%5,%6,%7}, {%8,%9}, {%0,%1,%2,%3};"
                 : "+f"(d[0]), "+f"(d[1]), "+f"(d[2]), "+f"(d[3])
                 : "r"(a[0]), "r"(a[1]), "r"(a[2]), "r"(a[3]), "r"(b[0]), "r"(b[1]));
}
__device__ __forceinline__ void cpa16(uint32_t saddr, const void* gptr) {
    asm volatile("cp.async.cg.shared.global [%0], [%1], 16;" :: "r"(saddr), "l"(gptr) : "memory");
}
#define CP_COMMIT() asm volatile("cp.async.commit_group;" ::: "memory")
#define CP_WAIT1()  asm volatile("cp.async.wait_group 1;" ::: "memory")
#define CP_WAIT0()  asm volatile("cp.async.wait_group 0;" ::: "memory")

__device__ __forceinline__ void split_bf16(float x, __nv_bfloat16& h, __nv_bfloat16& l) {
    h = __float2bfloat16(x);
    l = __float2bfloat16(x - __bfloat162float(h));
}

// ---------------- double-buffered warp-MMA split-bf16 GEMM, pass-major MMA issue ----------------
#define SSTR 40
#define STAGE_B 40960
#define HMMA_SMEM (2*STAGE_B)
__global__ void __launch_bounds__(256)
hmma_gemm(const __nv_bfloat16* __restrict__ Ahi, const __nv_bfloat16* __restrict__ Alo, int lda,
          const __nv_bfloat16* __restrict__ Bhi, const __nv_bfloat16* __restrict__ Blo, int ldb,
          float* __restrict__ C, int ldc, int Nreal, int Klen, size_t zstride,
          const float* __restrict__ bias)
{
    extern __shared__ char dsm[];
    const uint32_t sb = s2u(dsm);

    const int tid = threadIdx.x, lane = tid & 31, wid = tid >> 5;
    const int bm = blockIdx.y * 128, bn = blockIdx.x * 128;
    const int kbase = blockIdx.z * Klen;
    C += (size_t)blockIdx.z * zstride;
    const int wm = (wid & 1) * 64, wn = (wid >> 1) * 32;

    float acc[4][4][4];
#pragma unroll
    for (int i = 0; i < 4; i++)
#pragma unroll
        for (int j = 0; j < 4; j++)
#pragma unroll
            for (int u = 0; u < 4; u++) acc[i][j][u] = 0.f;

    const int l15 = lane & 15, lq = lane >> 4;
    const int l8 = lane & 7, sel = lane >> 3;
    const int row0 = tid >> 2, q0 = tid & 3;
    const int row1 = row0 + 64, q1 = q0;
    const int ntiles = Klen >> 5;

    {
        size_t ga0 = (size_t)(bm + row0) * lda + kbase + q0 * 8;
        size_t gb0 = (size_t)(bn + row0) * ldb + kbase + q0 * 8;
        size_t ga1 = (size_t)(bm + row1) * lda + kbase + q1 * 8;
        size_t gb1 = (size_t)(bn + row1) * ldb + kbase + q1 * 8;
        uint32_t s0 = sb + (uint32_t)(row0 * SSTR + q0 * 8) * 2;
        uint32_t s1 = sb + (uint32_t)(row1 * SSTR + q1 * 8) * 2;
        cpa16(s0,         Ahi + ga0); cpa16(s0 + 10240, Alo + ga0);
        cpa16(s0 + 20480, Bhi + gb0); cpa16(s0 + 30720, Blo + gb0);
        cpa16(s1,         Ahi + ga1); cpa16(s1 + 10240, Alo + ga1);
        cpa16(s1 + 20480, Bhi + gb1); cpa16(s1 + 30720, Blo + gb1);
        CP_COMMIT();
    }

    for (int t = 0; t < ntiles; t++) {
        if (t + 1 < ntiles) {
            int kt = kbase + (t + 1) * 32;
            uint32_t stb = sb + ((t + 1) & 1) * STAGE_B;
            size_t ga0 = (size_t)(bm + row0) * lda + kt + q0 * 8;
            size_t gb0 = (size_t)(bn + row0) * ldb + kt + q0 * 8;
            size_t ga1 = (size_t)(bm + row1) * lda + kt + q1 * 8;
            size_t gb1 = (size_t)(bn + row1) * ldb + kt + q1 * 8;
            uint32_t s0 = stb + (uint32_t)(row0 * SSTR + q0 * 8) * 2;
            uint32_t s1 = stb + (uint32_t)(row1 * SSTR + q1 * 8) * 2;
            cpa16(s0,         Ahi + ga0); cpa16(s0 + 10240, Alo + ga0);
            cpa16(s0 + 20480, Bhi + gb0); cpa16(s0 + 30720, Blo + gb0);
            cpa16(s1,         Ahi + ga1); cpa16(s1 + 10240, Alo + ga1);
            cpa16(s1 + 20480, Bhi + gb1); cpa16(s1 + 30720, Blo + gb1);
            CP_COMMIT();
            CP_WAIT1();
        } else {
            CP_WAIT0();
        }
        __syncthreads();

        const uint32_t stb = sb + (t & 1) * STAGE_B;
        const uint32_t aHi = stb, aLo = stb + 10240, bHi = stb + 20480, bLo = stb + 30720;

#pragma unroll
        for (int ks = 0; ks < 2; ks++) {
            uint32_t ahi[4][4], alo[4][4];
#pragma unroll
            for (int mf = 0; mf < 4; mf++) {
                uint32_t off = (uint32_t)((wm + mf * 16 + l15) * SSTR + ks * 16 + lq * 8) * 2;
                ldm4(ahi[mf], aHi + off);
                ldm4(alo[mf], aLo + off);
            }
            uint32_t bhi[4][2], blo[4][2];
#pragma unroll
            for (int p = 0; p < 2; p++) {
                uint32_t off = (uint32_t)((wn + p * 16 + (sel >> 1) * 8 + l8) * SSTR
                                          + ks * 16 + (sel & 1) * 8) * 2;
                uint32_t r[4];
                ldm4(r, bHi + off);
                bhi[p*2][0] = r[0]; bhi[p*2][1] = r[1];
                bhi[p*2+1][0] = r[2]; bhi[p*2+1][1] = r[3];
                ldm4(r, bLo + off);
                blo[p*2][0] = r[0]; blo[p*2][1] = r[1];
                blo[p*2+1][0] = r[2]; blo[p*2+1][1] = r[3];
            }
            // pass-major issue: 16 independent MMAs per pass; RAW distance = 16
#pragma unroll
            for (int mf = 0; mf < 4; mf++)
#pragma unroll
                for (int nf = 0; nf < 4; nf++)
                    mma_bf16(acc[mf][nf], ahi[mf], bhi[nf]);
#pragma unroll
            for (int mf = 0; mf < 4; mf++)
#pragma unroll
                for (int nf = 0; nf < 4; nf++)
                    mma_bf16(acc[mf][nf], ahi[mf], blo[nf]);
#pragma unroll
            for (int mf = 0; mf < 4; mf++)
#pragma unroll
                for (int nf = 0; nf < 4; nf++)
                    mma_bf16(acc[mf][nf], alo[mf], bhi[nf]);
        }
        __syncthreads();
    }

    const int crow = lane >> 2, ccol = (lane & 3) * 2;
#pragma unroll
    for (int mf = 0; mf < 4; mf++) {
        int r0 = bm + wm + mf * 16 + crow;
#pragma unroll
        for (int nf = 0; nf < 4; nf++) {
            int c0 = bn + wn + nf * 8 + ccol;
#pragma unroll
            for (int half = 0; half < 2; half++) {
                int r = r0 + half * 8;
#pragma unroll
                for (int u = 0; u < 2; u++) {
                    int n = c0 + u;
                    if (n < Nreal) {
                        float v = acc[mf][nf][half * 2 + u];
                        if (bias) v += bias[n];
                        C[(size_t)r * ldc + n] = v;
                    }
                }
            }
        }
    }
}

// ---------------- prep / elementwise kernels ----------------
__global__ void prep_bias_kernel(const float* __restrict__ b_ih, const float* __restrict__ b_hh) {
    int idx = blockIdx.x * 256 + threadIdx.x;
    if (idx < 4 * E) g_biassum[idx] = b_ih[idx] + b_hh[idx];
}

__global__ void conv_fc2w_kernel(const float* __restrict__ fc2_w) {
    int idx = blockIdx.x * 256 + threadIdx.x;
    int r = idx >> 8, c = idx & 255;
    float v = (r < RP1) ? fc2_w[r * E + c] : 0.f;
    split_bf16(v, g_fc2whi[idx], g_fc2wlo[idx]);
}

__global__ void conv_wih_kernel(const float* __restrict__ w_ih) {
    int idx = blockIdx.x * 256 + threadIdx.x;
    split_bf16(w_ih[idx], g_wihhi[idx], g_wihlo[idx]);
}

__global__ void conv_embT_kernel(const float* __restrict__ emb_w) {
    __shared__ float tile[32][33];
    int k0 = blockIdx.x * 32, e0 = blockIdx.y * 32;
    int tx = threadIdx.x & 31, ty = threadIdx.x >> 5;
#pragma unroll
    for (int r = 0; r < 32; r += 8) {
        int k = k0 + ty + r;
        tile[ty + r][tx] = (k < Rr) ? emb_w[(size_t)k * E + e0 + tx] : 0.f;
    }
    __syncthreads();
#pragma unroll
    for (int r = 0; r < 32; r += 8) {
        int e = e0 + ty + r;
        float v = tile[tx][ty + r];
        split_bf16(v, g_embThi[(size_t)e * KPAD + k0 + tx],
                      g_embTlo[(size_t)e * KPAD + k0 + tx]);
    }
}

__global__ void embed_kernel(const int* __restrict__ bodys, const float* __restrict__ emb_w) {
    int idx = blockIdx.x * 256 + threadIdx.x;
    int e = idx & 255, b = (idx >> 8) & 1023, t = idx >> 18;
    float v = emb_w[(size_t)bodys[b * L + t] * E + e];
    g_xT[idx] = v;
    split_bf16(v, g_xhi[idx], g_xlo[idx]);
    if (idx < Bb * E) { g_h[idx] = 0.f; g_c[idx] = 0.f; }
}

__device__ __forceinline__ float sigm(float x) { return 1.f / (1.f + __expf(-x)); }

__global__ void lstm_cell_kernel(int t) {
    int idx = blockIdx.x * 256 + threadIdx.x;      // B*E
    int b = idx >> 8, e = idx & 255;
    const float* g = g_gates + b * (4 * E);
    float gi = g[e], gf = g[E + e], gg = g[2 * E + e], go = g[3 * E + e];
    float cc = sigm(gf) * g_c[idx] + sigm(gi) * tanhf(gg);
    float hh = sigm(go) * tanhf(cc);
    g_c[idx] = cc; g_h[idx] = hh;
    g_hid[b * (L * E) + t * E + e] = hh;
}

__global__ void concat0_kernel(float* __restrict__ out_emb) {
    int idx = blockIdx.x * 256 + threadIdx.x;
    int b = idx >> 9, j = idx & 511;
    out_emb[idx] = (j < E) ? g_xT[b * E + j] : g_xT[(1024 + b) * E + (j - E)];
}

__global__ void emb1_finish_kernel(float* __restrict__ out_emb,
                                   const float* __restrict__ emb_w, int i) {
    int idx = blockIdx.x * 256 + threadIdx.x;
    int b = idx >> 8, e = idx & 255;
    float s = 0.f;
#pragma unroll
    for (int p = 0; p < SPLITK; p++) s += g_part[p * (Bb * E) + idx];
    s += g_psflast[b] * g_hid[b * (L * E) + i * E + e];
    out_emb[b * (2 * E) + e]     = s;
    out_emb[b * (2 * E) + E + e] = emb_w[(i + 1) * E + e];
}

// online softmax: one fused max+sum pass, one write pass
__global__ void softmax_kernel(const float* __restrict__ prob) {
    int b = blockIdx.x;
    const float* row = prob + (size_t)b * RP1;
    __nv_bfloat16* ohi = g_psfhi + (size_t)b * KPAD;
    __nv_bfloat16* olo = g_psflo + (size_t)b * KPAD;
    __shared__ float rm[256], rs[256];
    int t = threadIdx.x;
    float m = -1e30f, s = 0.f;
    for (int j = t; j < RP1; j += 256) {
        float x = row[j];
        float mn = fmaxf(m, x);
        s = s * __expf(m - mn) + __expf(x - mn);
        m = mn;
    }
    rm[t] = m; rs[t] = s; __syncthreads();
    for (int st = 128; st > 0; st >>= 1) {
        if (t < st) {
            float m2 = rm[t + st], s2 = rs[t + st];
            float mn = fmaxf(rm[t], m2);
            rs[t] = rs[t] * __expf(rm[t] - mn) + s2 * __expf(m2 - mn);
            rm[t] = mn;
        }
        __syncthreads();
    }
    m = rm[0];
    float inv = 1.f / rs[0];
    for (int j = t; j < KPAD; j += 256) {
        if (j < Rr) {
            float v = __expf(row[j] - m) * inv;
            split_bf16(v, ohi[j], olo[j]);
        } else {
            if (j == Rr) g_psflast[b] = __expf(row[j] - m) * inv;
            ohi[j] = __float2bfloat16(0.f);
            olo[j] = __float2bfloat16(0.f);
        }
    }
}

// ---------------- 64x64 FFMA2 GEMM (LSTM step, fc1) ----------------
#define BMT 64
#define BNT 64
#define BKT 16
template<bool TRANSB, bool RELU>
__global__ void gemm_kernel(const float* __restrict__ A, int lda,
                            const float* __restrict__ B, int ldb,
                            float* __restrict__ C, int ldc,
                            int M, int N, int Klen,
                            const float* __restrict__ bias,
                            const float* __restrict__ Cin, int ldcin,
                            __nv_bfloat16* __restrict__ Ohi,
                            __nv_bfloat16* __restrict__ Olo)
{
    __shared__ float As[BKT][BMT + 4];
    __shared__ float Bs[BKT][BNT + 4];
    int bm = blockIdx.y * BMT, bn = blockIdx.x * BNT;
    int tid = threadIdx.x;
    int tx = tid & 15, ty = tid >> 4;
    unsigned long long acc[4][2];
#pragma unroll
    for (int i = 0; i < 4; i++) { acc[i][0] = 0ULL; acc[i][1] = 0ULL; }

    for (int kt = 0; kt < Klen; kt += BKT) {
#pragma unroll
        for (int j = 0; j < 4; j++) {
            int idx = tid + j * 256;
            int m = idx >> 4, k = idx & 15;
            As[k][m] = A[(size_t)(bm + m) * lda + kt + k];
        }
#pragma unroll
        for (int j = 0; j < 4; j++) {
            int idx = tid + j * 256;
            if (TRANSB) {
                int n = idx >> 4, k = idx & 15;
                Bs[k][n] = (bn + n < N) ? B[(size_t)(bn + n) * ldb + kt + k] : 0.f;
            } else {
                int k = idx >> 6, n = idx & 63;
                Bs[k][n] = (bn + n < N) ? B[(size_t)(kt + k) * ldb + bn + n] : 0.f;
            }
        }
        __syncthreads();
#pragma unroll
        for (int kk = 0; kk < BKT; kk++) {
            float4 a4 = *(const float4*)&As[kk][ty * 4];
            float4 b4 = *(const float4*)&Bs[kk][tx * 4];
            unsigned long long bp0, bp1;
            PACKF2(bp0, b4.x, b4.y); PACKF2(bp1, b4.z, b4.w);
            float av[4] = {a4.x, a4.y, a4.z, a4.w};
#pragma unroll
            for (int i = 0; i < 4; i++) {
                unsigned long long a2;
                PACKF2(a2, av[i], av[i]);
                FMAF2(acc[i][0], a2, bp0);
                FMAF2(acc[i][1], a2, bp1);
            }
        }
        __syncthreads();
    }
#pragma unroll
    for (int i = 0; i < 4; i++) {
        int m = bm + ty * 4 + i;
#pragma unroll
        for (int j = 0; j < 2; j++) {
            int nbase = bn + tx * 4 + 2 * j;
            float lo, hi;
            UNPACKF2(lo, hi, acc[i][j]);
#pragma unroll
            for (int u = 0; u < 2; u++) {
                int n = nbase + u;
                if (n < N) {
                    float v = (u == 0) ? lo : hi;
                    if (Cin) v += Cin[(size_t)m * ldcin + n];
                    else if (bias) v += bias[n];
                    if (RELU) v = fmaxf(v, 0.f);
                    if (Ohi) {
                        __nv_bfloat16 vh, vl;
                        split_bf16(v, vh, vl);
                        Ohi[(size_t)m * ldc + n] = vh;
                        Olo[(size_t)m * ldc + n] = vl;
                    } else {
                        C[(size_t)m * ldc + n] = v;
                    }
                }
            }
        }
    }
}

// ---------------- launch ----------------
extern "C" void kernel_launch(void* const* d_in, const int* in_sizes, int n_in,
                              void* d_out, int out_size) {
    const int*   bodys = (const int*)  d_in[0];
    const float* emb_w = (const float*)d_in[1];
    const float* w_ih  = (const float*)d_in[2];
    const float* w_hh  = (const float*)d_in[3];
    const float* b_ih  = (const float*)d_in[4];
    const float* b_hh  = (const float*)d_in[5];
    const float* fc1_w = (const float*)d_in[6];
    const float* fc1_b = (const float*)d_in[7];
    const float* fc2_w = (const float*)d_in[8];
    const float* fc2_b = (const float*)d_in[9];

    float* out_prob = (float*)d_out;
    float* out_emb  = out_prob + (size_t)Bb * RP1;

    cudaFuncSetAttribute(hmma_gemm, cudaFuncAttributeMaxDynamicSharedMemorySize, HMMA_SMEM);

    float *biassum, *part, *gx, *h, *gates;
    __nv_bfloat16 *xhi, *xlo, *h1hi, *h1lo, *psfhi, *psflo, *eThi, *eTlo, *f2hi, *f2lo, *wihhi, *wihlo;
    cudaGetSymbolAddress((void**)&biassum, g_biassum);
    cudaGetSymbolAddress((void**)&part,    g_part);
    cudaGetSymbolAddress((void**)&gx,      g_gx);
    cudaGetSymbolAddress((void**)&h,       g_h);
    cudaGetSymbolAddress((void**)&gates,   g_gates);
    cudaGetSymbolAddress((void**)&xhi,     g_xhi);
    cudaGetSymbolAddress((void**)&xlo,     g_xlo);
    cudaGetSymbolAddress((void**)&h1hi,    g_h1hi);
    cudaGetSymbolAddress((void**)&h1lo,    g_h1lo);
    cudaGetSymbolAddress((void**)&psfhi,   g_psfhi);
    cudaGetSymbolAddress((void**)&psflo,   g_psflo);
    cudaGetSymbolAddress((void**)&eThi,    g_embThi);
    cudaGetSymbolAddress((void**)&eTlo,    g_embTlo);
    cudaGetSymbolAddress((void**)&f2hi,    g_fc2whi);
    cudaGetSymbolAddress((void**)&f2lo,    g_fc2wlo);
    cudaGetSymbolAddress((void**)&wihhi,   g_wihhi);
    cudaGetSymbolAddress((void**)&wihlo,   g_wihlo);

    // launch order keeps the gx HMMA in the profiler's capture slot (4th launch)
    prep_bias_kernel<<<4, 256>>>(b_ih, b_hh);
    conv_wih_kernel<<<(4 * E * E) / 256, 256>>>(w_ih);
    embed_kernel<<<8192, 256>>>(bodys, emb_w);
    hmma_gemm<<<dim3(8, 64), 256, HMMA_SMEM>>>(
        xhi, xlo, E, wihhi, wihlo, E,
        gx, 4 * E, 4 * E, E, 0, biassum);
    conv_fc2w_kernel<<<(NPADW * E) / 256, 256>>>(fc2_w);
    conv_embT_kernel<<<dim3(KPAD / 32, E / 32), 256>>>(emb_w);

    // LSTM steps: gates = h @ w_hh^T + gx_t : FFMA2 full-chip + cell
    for (int t = 0; t < L; t++) {
        gemm_kernel<true, false><<<dim3(16, 16), 256>>>(
            h, E, w_hh, E, gates, 4 * E, Bb, 4 * E, E,
            nullptr, gx + (size_t)t * Bb * 4 * E, 4 * E, nullptr, nullptr);
        lstm_cell_kernel<<<1024, 256>>>(t);
    }

    for (int i = 0; i < L - 1; i++) {
        if (i == 0) {
            concat0_kernel<<<2048, 256>>>(out_emb);
        } else {
            hmma_gemm<<<dim3(2, 8, SPLITK), 256, HMMA_SMEM>>>(
                psfhi, psflo, KPAD, eThi, eTlo, KPAD,
                part, E, E, KSPL, (size_t)Bb * E, nullptr);
            emb1_finish_kernel<<<1024, 256>>>(out_emb, emb_w, i);
        }
        // hidden1 = relu(emb_concat @ fc1_w^T + fc1_b) -> split bf16 direct
        gemm_kernel<true, true><<<dim3(4, 16), 256>>>(
            out_emb, 2 * E, fc1_w, 2 * E, nullptr, E, Bb, E, 2 * E,
            fc1_b, nullptr, 0, h1hi, h1lo);
        // prob = hidden1 @ fc2_w^T + fc2_b
        hmma_gemm<<<dim3(79, 8), 256, HMMA_SMEM>>>(
            h1hi, h1lo, E, f2hi, f2lo, E,
            out_prob, RP1, RP1, E, 0, fc2_b);
        if (i < L - 2) softmax_kernel<<<1024, 256>>>(out_prob);
    }
}

// round 10
// speedup vs baseline: 1.2228x; 1.1753x over previous
#include <cuda_runtime.h>
#include <cuda_bf16.h>
#include <math.h>
#include <stdint.h>

#define Rr   10000
#define E    256
#define Bb   1024
#define L    8
#define RP1  10001
#define KPAD 10240            // padded K for probsf@emb_w (mult of 32)
#define NPADW 10112           // fc2_w rows padded (>= 157*64)
#define SPLITK 10
#define KSPL 1024             // KPAD / SPLITK
#define FC1SPLIT 4
#define FC1KSPL 128           // 512 / 4

// packed f32x2 helpers (Blackwell FFMA2)
#define PACKF2(d, lo, hi) asm("mov.b64 %0, {%1, %2};" : "=l"(d) : "f"(lo), "f"(hi))
#define FMAF2(acc, a, b)  asm("fma.rn.f32x2 %0, %1, %2, %0;" : "+l"(acc) : "l"(a), "l"(b))
#define UNPACKF2(lo, hi, v) asm("mov.b64 {%0, %1}, %2;" : "=f"(lo), "=f"(hi) : "l"(v))

// ---------------- scratch ----------------
__device__ float g_xT[Bb*L*E];
__device__ __nv_bfloat16 g_xhi[Bb*L*E];
__device__ __nv_bfloat16 g_xlo[Bb*L*E];
__device__ float g_hid[Bb*L*E];
__device__ float g_h[Bb*E];
__device__ float g_c[Bb*E];
__device__ float g_gates[Bb*4*E];
__device__ float g_gx[(size_t)Bb*L*4*E];
__device__ __nv_bfloat16 g_h1hi[Bb*E];
__device__ __nv_bfloat16 g_h1lo[Bb*E];
__device__ __nv_bfloat16 g_psfhi[(size_t)Bb*KPAD];
__device__ __nv_bfloat16 g_psflo[(size_t)Bb*KPAD];
__device__ float g_psflast[Bb];
__device__ __nv_bfloat16 g_embThi[(size_t)E*KPAD];
__device__ __nv_bfloat16 g_embTlo[(size_t)E*KPAD];
__device__ __nv_bfloat16 g_fc2whi[(size_t)NPADW*E];
__device__ __nv_bfloat16 g_fc2wlo[(size_t)NPADW*E];
__device__ __nv_bfloat16 g_wihhi[4*E*E];
__device__ __nv_bfloat16 g_wihlo[4*E*E];
__device__ float g_biassum[4*E];
__device__ float g_part[SPLITK*Bb*E];

// ---------------- ptx helpers ----------------
__device__ __forceinline__ uint32_t s2u(const void* p) {
    uint32_t a;
    asm("{ .reg .u64 t; cvta.to.shared.u64 t, %1; cvt.u32.u64 %0, t; }" : "=r"(a) : "l"(p));
    return a;
}
__device__ __forceinline__ void ldm4(uint32_t* r, uint32_t addr) {
    asm volatile("ldmatrix.sync.aligned.m8n8.x4.shared.b16 {%0,%1,%2,%3}, [%4];"
                 : "=r"(r[0]), "=r"(r[1]), "=r"(r[2]), "=r"(r[3]) : "r"(addr));
}
__device__ __forceinline__ void mma_bf16(float* d, const uint32_t* a, const uint32_t* b) {
    asm volatile("mma.sync.aligned.m16n8k16.row.col.f32.bf16.bf16.f32 "
                 "{%0,%1,%2,%3}, {%4,%5,%6,%7}, {%8,%9}, {%0,%1,%2,%3};"
                 : "+f"(d[0]), "+f"(d[1]), "+f"(d[2]), "+f"(d[3])
                 : "r"(a[0]), "r"(a[1]), "r"(a[2]), "r"(a[3]), "r"(b[0]), "r"(b[1]));
}
__device__ __forceinline__ void cpa16(uint32_t saddr, const void* gptr) {
    asm volatile("cp.async.cg.shared.global [%0], [%1], 16;" :: "r"(saddr), "l"(gptr) : "memory");
}
#define CP_COMMIT() asm volatile("cp.async.commit_group;" ::: "memory")
#define CP_WAIT1()  asm volatile("cp.async.wait_group 1;" ::: "memory")
#define CP_WAIT0()  asm volatile("cp.async.wait_group 0;" ::: "memory")

__device__ __forceinline__ void split_bf16(float x, __nv_bfloat16& h, __nv_bfloat16& l) {
    h = __float2bfloat16(x);
    l = __float2bfloat16(x - __bfloat162float(h));
}

// ---------------- 128x64-tile double-buffered warp-MMA split-bf16 GEMM ----------------
// 8 warps as 4(M)x2(N); warp tile 32x32. 3 CTAs/SM (60KB smem).
#define SSTR 40
#define OFF_ALO 10240
#define OFF_BHI 20480
#define OFF_BLO 25600
#define STAGE_B 30720
#define HMMA_SMEM (2*STAGE_B)
__global__ void __launch_bounds__(256)
hmma_gemm(const __nv_bfloat16* __restrict__ Ahi, const __nv_bfloat16* __restrict__ Alo, int lda,
          const __nv_bfloat16* __restrict__ Bhi, const __nv_bfloat16* __restrict__ Blo, int ldb,
          float* __restrict__ C, int ldc, int Nreal, int Klen, size_t zstride,
          const float* __restrict__ bias)
{
    extern __shared__ char dsm[];
    const uint32_t sb = s2u(dsm);

    const int tid = threadIdx.x, lane = tid & 31, wid = tid >> 5;
    const int bm = blockIdx.y * 128, bn = blockIdx.x * 64;
    const int kbase = blockIdx.z * Klen;
    C += (size_t)blockIdx.z * zstride;
    const int wm = (wid & 3) * 32, wn = (wid >> 2) * 32;

    float acc[2][4][4];
#pragma unroll
    for (int i = 0; i < 2; i++)
#pragma unroll
        for (int j = 0; j < 4; j++)
#pragma unroll
            for (int u = 0; u < 4; u++) acc[i][j][u] = 0.f;

    const int l15 = lane & 15, lq = lane >> 4;
    const int l8 = lane & 7, sel = lane >> 3;
    // A loads: 128 rows x 4 chunks = 512 / 256 threads = 2 each
    const int arow0 = tid >> 2, aq0 = tid & 3;
    const int arow1 = arow0 + 64;
    // B loads: 64 rows x 4 chunks = 256 / 256 = 1 each
    const int brow = tid >> 2, bq = tid & 3;
    const int ntiles = Klen >> 5;

    {
        size_t ga0 = (size_t)(bm + arow0) * lda + kbase + aq0 * 8;
        size_t ga1 = (size_t)(bm + arow1) * lda + kbase + aq0 * 8;
        size_t gb  = (size_t)(bn + brow) * ldb + kbase + bq * 8;
        uint32_t sa0 = sb + (uint32_t)(arow0 * SSTR + aq0 * 8) * 2;
        uint32_t sa1 = sb + (uint32_t)(arow1 * SSTR + aq0 * 8) * 2;
        uint32_t sbb = sb + (uint32_t)(brow * SSTR + bq * 8) * 2;
        cpa16(sa0,           Ahi + ga0); cpa16(sa0 + OFF_ALO, Alo + ga0);
        cpa16(sa1,           Ahi + ga1); cpa16(sa1 + OFF_ALO, Alo + ga1);
        cpa16(sbb + OFF_BHI, Bhi + gb);  cpa16(sbb + OFF_BLO, Blo + gb);
        CP_COMMIT();
    }

    for (int t = 0; t < ntiles; t++) {
        if (t + 1 < ntiles) {
            int kt = kbase + (t + 1) * 32;
            uint32_t stb = sb + ((t + 1) & 1) * STAGE_B;
            size_t ga0 = (size_t)(bm + arow0) * lda + kt + aq0 * 8;
            size_t ga1 = (size_t)(bm + arow1) * lda + kt + aq0 * 8;
            size_t gb  = (size_t)(bn + brow) * ldb + kt + bq * 8;
            uint32_t sa0 = stb + (uint32_t)(arow0 * SSTR + aq0 * 8) * 2;
            uint32_t sa1 = stb + (uint32_t)(arow1 * SSTR + aq0 * 8) * 2;
            uint32_t sbb = stb + (uint32_t)(brow * SSTR + bq * 8) * 2;
            cpa16(sa0,           Ahi + ga0); cpa16(sa0 + OFF_ALO, Alo + ga0);
            cpa16(sa1,           Ahi + ga1); cpa16(sa1 + OFF_ALO, Alo + ga1);
            cpa16(sbb + OFF_BHI, Bhi + gb);  cpa16(sbb + OFF_BLO, Blo + gb);
            CP_COMMIT();
            CP_WAIT1();
        } else {
            CP_WAIT0();
        }
        __syncthreads();

        const uint32_t stb = sb + (t & 1) * STAGE_B;
        const uint32_t aHi = stb, aLo = stb + OFF_ALO, bHi = stb + OFF_BHI, bLo = stb + OFF_BLO;

#pragma unroll
        for (int ks = 0; ks < 2; ks++) {
            uint32_t ahi[2][4], alo[2][4];
#pragma unroll
            for (int mf = 0; mf < 2; mf++) {
                uint32_t off = (uint32_t)((wm + mf * 16 + l15) * SSTR + ks * 16 + lq * 8) * 2;
                ldm4(ahi[mf], aHi + off);
                ldm4(alo[mf], aLo + off);
            }
            uint32_t bhi[4][2], blo[4][2];
#pragma unroll
            for (int p = 0; p < 2; p++) {
                uint32_t off = (uint32_t)((wn + p * 16 + (sel >> 1) * 8 + l8) * SSTR
                                          + ks * 16 + (sel & 1) * 8) * 2;
                uint32_t r[4];
                ldm4(r, bHi + off);
                bhi[p*2][0] = r[0]; bhi[p*2][1] = r[1];
                bhi[p*2+1][0] = r[2]; bhi[p*2+1][1] = r[3];
                ldm4(r, bLo + off);
                blo[p*2][0] = r[0]; blo[p*2][1] = r[1];
                blo[p*2+1][0] = r[2]; blo[p*2+1][1] = r[3];
            }
#pragma unroll
            for (int mf = 0; mf < 2; mf++)
#pragma unroll
                for (int nf = 0; nf < 4; nf++)
                    mma_bf16(acc[mf][nf], ahi[mf], bhi[nf]);
#pragma unroll
            for (int mf = 0; mf < 2; mf++)
#pragma unroll
                for (int nf = 0; nf < 4; nf++)
                    mma_bf16(acc[mf][nf], ahi[mf], blo[nf]);
#pragma unroll
            for (int mf = 0; mf < 2; mf++)
#pragma unroll
                for (int nf = 0; nf < 4; nf++)
                    mma_bf16(acc[mf][nf], alo[mf], bhi[nf]);
        }
        __syncthreads();
    }

    const int crow = lane >> 2, ccol = (lane & 3) * 2;
#pragma unroll
    for (int mf = 0; mf < 2; mf++) {
        int r0 = bm + wm + mf * 16 + crow;
#pragma unroll
        for (int nf = 0; nf < 4; nf++) {
            int c0 = bn + wn + nf * 8 + ccol;
#pragma unroll
            for (int half = 0; half < 2; half++) {
                int r = r0 + half * 8;
#pragma unroll
                for (int u = 0; u < 2; u++) {
                    int n = c0 + u;
                    if (n < Nreal) {
                        float v = acc[mf][nf][half * 2 + u];
                        if (bias) v += bias[n];
                        C[(size_t)r * ldc + n] = v;
                    }
                }
            }
        }
    }
}

// ---------------- prep / elementwise kernels ----------------
__global__ void prep_bias_kernel(const float* __restrict__ b_ih, const float* __restrict__ b_hh) {
    int idx = blockIdx.x * 256 + threadIdx.x;
    if (idx < 4 * E) g_biassum[idx] = b_ih[idx] + b_hh[idx];
}

__global__ void conv_fc2w_kernel(const float* __restrict__ fc2_w) {
    int idx = blockIdx.x * 256 + threadIdx.x;
    int r = idx >> 8, c = idx & 255;
    float v = (r < RP1) ? fc2_w[r * E + c] : 0.f;
    split_bf16(v, g_fc2whi[idx], g_fc2wlo[idx]);
}

__global__ void conv_wih_kernel(const float* __restrict__ w_ih) {
    int idx = blockIdx.x * 256 + threadIdx.x;
    split_bf16(w_ih[idx], g_wihhi[idx], g_wihlo[idx]);
}

__global__ void conv_embT_kernel(const float* __restrict__ emb_w) {
    __shared__ float tile[32][33];
    int k0 = blockIdx.x * 32, e0 = blockIdx.y * 32;
    int tx = threadIdx.x & 31, ty = threadIdx.x >> 5;
#pragma unroll
    for (int r = 0; r < 32; r += 8) {
        int k = k0 + ty + r;
        tile[ty + r][tx] = (k < Rr) ? emb_w[(size_t)k * E + e0 + tx] : 0.f;
    }
    __syncthreads();
#pragma unroll
    for (int r = 0; r < 32; r += 8) {
        int e = e0 + ty + r;
        float v = tile[tx][ty + r];
        split_bf16(v, g_embThi[(size_t)e * KPAD + k0 + tx],
                      g_embTlo[(size_t)e * KPAD + k0 + tx]);
    }
}

__global__ void embed_kernel(const int* __restrict__ bodys, const float* __restrict__ emb_w) {
    int idx = blockIdx.x * 256 + threadIdx.x;
    int e = idx & 255, b = (idx >> 8) & 1023, t = idx >> 18;
    float v = emb_w[(size_t)bodys[b * L + t] * E + e];
    g_xT[idx] = v;
    split_bf16(v, g_xhi[idx], g_xlo[idx]);
    if (idx < Bb * E) { g_h[idx] = 0.f; g_c[idx] = 0.f; }
}

__device__ __forceinline__ float sigm(float x) { return 1.f / (1.f + __expf(-x)); }

__global__ void lstm_cell_kernel(int t) {
    int idx = blockIdx.x * 256 + threadIdx.x;
    int b = idx >> 8, e = idx & 255;
    const float* g = g_gates + b * (4 * E);
    float gi = g[e], gf = g[E + e], gg = g[2 * E + e], go = g[3 * E + e];
    float cc = sigm(gf) * g_c[idx] + sigm(gi) * tanhf(gg);
    float hh = sigm(go) * tanhf(cc);
    g_c[idx] = cc; g_h[idx] = hh;
    g_hid[b * (L * E) + t * E + e] = hh;
}

__global__ void concat0_kernel(float* __restrict__ out_emb) {
    int idx = blockIdx.x * 256 + threadIdx.x;
    int b = idx >> 9, j = idx & 511;
    out_emb[idx] = (j < E) ? g_xT[b * E + j] : g_xT[(1024 + b) * E + (j - E)];
}

__global__ void emb1_finish_kernel(float* __restrict__ out_emb,
                                   const float* __restrict__ emb_w, int i) {
    int idx = blockIdx.x * 256 + threadIdx.x;
    int b = idx >> 8, e = idx & 255;
    float s = 0.f;
#pragma unroll
    for (int p = 0; p < SPLITK; p++) s += g_part[p * (Bb * E) + idx];
    s += g_psflast[b] * g_hid[b * (L * E) + i * E + e];
    out_emb[b * (2 * E) + e]     = s;
    out_emb[b * (2 * E) + E + e] = emb_w[(i + 1) * E + e];
}

__global__ void fc1_finish_kernel(const float* __restrict__ fc1_b) {
    int idx = blockIdx.x * 256 + threadIdx.x;      // B*E
    int e = idx & 255;
    float s = fc1_b[e];
#pragma unroll
    for (int p = 0; p < FC1SPLIT; p++) s += g_part[p * (Bb * E) + idx];
    s = fmaxf(s, 0.f);
    split_bf16(s, g_h1hi[idx], g_h1lo[idx]);
}

// online softmax
__global__ void softmax_kernel(const float* __restrict__ prob) {
    int b = blockIdx.x;
    const float* row = prob + (size_t)b * RP1;
    __nv_bfloat16* ohi = g_psfhi + (size_t)b * KPAD;
    __nv_bfloat16* olo = g_psflo + (size_t)b * KPAD;
    __shared__ float rm[256], rs[256];
    int t = threadIdx.x;
    float m = -1e30f, s = 0.f;
    for (int j = t; j < RP1; j += 256) {
        float x = row[j];
        float mn = fmaxf(m, x);
        s = s * __expf(m - mn) + __expf(x - mn);
        m = mn;
    }
    rm[t] = m; rs[t] = s; __syncthreads();
    for (int st = 128; st > 0; st >>= 1) {
        if (t < st) {
            float m2 = rm[t + st], s2 = rs[t + st];
            float mn = fmaxf(rm[t], m2);
            rs[t] = rs[t] * __expf(rm[t] - mn) + s2 * __expf(m2 - mn);
            rm[t] = mn;
        }
        __syncthreads();
    }
    m = rm[0];
    float inv = 1.f / rs[0];
    for (int j = t; j < KPAD; j += 256) {
        if (j < Rr) {
            float v = __expf(row[j] - m) * inv;
            split_bf16(v, ohi[j], olo[j]);
        } else {
            if (j == Rr) g_psflast[b] = __expf(row[j] - m) * inv;
            ohi[j] = __float2bfloat16(0.f);
            olo[j] = __float2bfloat16(0.f);
        }
    }
}

// ---------------- 64x64 FFMA2 GEMM with split-K + optional addend ----------------
#define BMT 64
#define BNT 64
#define BKT 16
template<bool TRANSB, bool RELU>
__global__ void gemm_kernel(const float* __restrict__ A, int lda,
                            const float* __restrict__ B, int ldb,
                            float* __restrict__ C, int ldc,
                            int M, int N, int Klen, size_t zstride,
                            const float* __restrict__ bias,
                            const float* __restrict__ Cin, int ldcin)
{
    __shared__ float As[BKT][BMT + 4];
    __shared__ float Bs[BKT][BNT + 4];
    int bm = blockIdx.y * BMT, bn = blockIdx.x * BNT;
    int kbase = blockIdx.z * Klen;
    C += (size_t)blockIdx.z * zstride;
    int tid = threadIdx.x;
    int tx = tid & 15, ty = tid >> 4;
    unsigned long long acc[4][2];
#pragma unroll
    for (int i = 0; i < 4; i++) { acc[i][0] = 0ULL; acc[i][1] = 0ULL; }

    for (int kt = 0; kt < Klen; kt += BKT) {
#pragma unroll
        for (int j = 0; j < 4; j++) {
            int idx = tid + j * 256;
            int m = idx >> 4, k = idx & 15;
            As[k][m] = A[(size_t)(bm + m) * lda + kbase + kt + k];
        }
#pragma unroll
        for (int j = 0; j < 4; j++) {
            int idx = tid + j * 256;
            if (TRANSB) {
                int n = idx >> 4, k = idx & 15;
                Bs[k][n] = (bn + n < N) ? B[(size_t)(bn + n) * ldb + kbase + kt + k] : 0.f;
            } else {
                int k = idx >> 6, n = idx & 63;
                Bs[k][n] = (bn + n < N) ? B[(size_t)(kbase + kt + k) * ldb + bn + n] : 0.f;
            }
        }
        __syncthreads();
#pragma unroll
        for (int kk = 0; kk < BKT; kk++) {
            float4 a4 = *(const float4*)&As[kk][ty * 4];
            float4 b4 = *(const float4*)&Bs[kk][tx * 4];
            unsigned long long bp0, bp1;
            PACKF2(bp0, b4.x, b4.y); PACKF2(bp1, b4.z, b4.w);
            float av[4] = {a4.x, a4.y, a4.z, a4.w};
#pragma unroll
            for (int i = 0; i < 4; i++) {
                unsigned long long a2;
                PACKF2(a2, av[i], av[i]);
                FMAF2(acc[i][0], a2, bp0);
                FMAF2(acc[i][1], a2, bp1);
            }
        }
        __syncthreads();
    }
#pragma unroll
    for (int i = 0; i < 4; i++) {
        int m = bm + ty * 4 + i;
#pragma unroll
        for (int j = 0; j < 2; j++) {
            int nbase = bn + tx * 4 + 2 * j;
            float lo, hi;
            UNPACKF2(lo, hi, acc[i][j]);
#pragma unroll
            for (int u = 0; u < 2; u++) {
                int n = nbase + u;
                if (n < N) {
                    float v = (u == 0) ? lo : hi;
                    if (Cin) v += Cin[(size_t)m * ldcin + n];
                    else if (bias) v += bias[n];
                    if (RELU) v = fmaxf(v, 0.f);
                    C[(size_t)m * ldc + n] = v;
                }
            }
        }
    }
}

// ---------------- launch ----------------
extern "C" void kernel_launch(void* const* d_in, const int* in_sizes, int n_in,
                              void* d_out, int out_size) {
    const int*   bodys = (const int*)  d_in[0];
    const float* emb_w = (const float*)d_in[1];
    const float* w_ih  = (const float*)d_in[2];
    const float* w_hh  = (const float*)d_in[3];
    const float* b_ih  = (const float*)d_in[4];
    const float* b_hh  = (const float*)d_in[5];
    const float* fc1_w = (const float*)d_in[6];
    const float* fc1_b = (const float*)d_in[7];
    const float* fc2_w = (const float*)d_in[8];
    const float* fc2_b = (const float*)d_in[9];

    float* out_prob = (float*)d_out;
    float* out_emb  = out_prob + (size_t)Bb * RP1;

    cudaFuncSetAttribute(hmma_gemm, cudaFuncAttributeMaxDynamicSharedMemorySize, HMMA_SMEM);

    float *biassum, *part, *gx, *h, *gates;
    __nv_bfloat16 *xhi, *xlo, *h1hi, *h1lo, *psfhi, *psflo, *eThi, *eTlo, *f2hi, *f2lo, *wihhi, *wihlo;
    cudaGetSymbolAddress((void**)&biassum, g_biassum);
    cudaGetSymbolAddress((void**)&part,    g_part);
    cudaGetSymbolAddress((void**)&gx,      g_gx);
    cudaGetSymbolAddress((void**)&h,       g_h);
    cudaGetSymbolAddress((void**)&gates,   g_gates);
    cudaGetSymbolAddress((void**)&xhi,     g_xhi);
    cudaGetSymbolAddress((void**)&xlo,     g_xlo);
    cudaGetSymbolAddress((void**)&h1hi,    g_h1hi);
    cudaGetSymbolAddress((void**)&h1lo,    g_h1lo);
    cudaGetSymbolAddress((void**)&psfhi,   g_psfhi);
    cudaGetSymbolAddress((void**)&psflo,   g_psflo);
    cudaGetSymbolAddress((void**)&eThi,    g_embThi);
    cudaGetSymbolAddress((void**)&eTlo,    g_embTlo);
    cudaGetSymbolAddress((void**)&f2hi,    g_fc2whi);
    cudaGetSymbolAddress((void**)&f2lo,    g_fc2wlo);
    cudaGetSymbolAddress((void**)&wihhi,   g_wihhi);
    cudaGetSymbolAddress((void**)&wihlo,   g_wihlo);

    // launch order keeps the gx HMMA in the profiler's capture slot (4th launch)
    prep_bias_kernel<<<4, 256>>>(b_ih, b_hh);
    conv_wih_kernel<<<(4 * E * E) / 256, 256>>>(w_ih);
    embed_kernel<<<8192, 256>>>(bodys, emb_w);
    hmma_gemm<<<dim3(16, 64), 256, HMMA_SMEM>>>(
        xhi, xlo, E, wihhi, wihlo, E,
        gx, 4 * E, 4 * E, E, 0, biassum);
    conv_fc2w_kernel<<<(NPADW * E) / 256, 256>>>(fc2_w);
    conv_embT_kernel<<<dim3(KPAD / 32, E / 32), 256>>>(emb_w);

    // LSTM steps: gates = h @ w_hh^T + gx_t : FFMA2 full-chip + cell
    for (int t = 0; t < L; t++) {
        gemm_kernel<true, false><<<dim3(16, 16), 256>>>(
            h, E, w_hh, E, gates, 4 * E, Bb, 4 * E, E, 0,
            nullptr, gx + (size_t)t * Bb * 4 * E, 4 * E);
        lstm_cell_kernel<<<1024, 256>>>(t);
    }

    for (int i = 0; i < L - 1; i++) {
        if (i == 0) {
            concat0_kernel<<<2048, 256>>>(out_emb);
        } else {
            hmma_gemm<<<dim3(4, 8, SPLITK), 256, HMMA_SMEM>>>(
                psfhi, psflo, KPAD, eThi, eTlo, KPAD,
                part, E, E, KSPL, (size_t)Bb * E, nullptr);
            emb1_finish_kernel<<<1024, 256>>>(out_emb, emb_w, i);
        }
        // fc1: split-K x4 partials, then finish (sum + bias + relu + split)
        gemm_kernel<true, false><<<dim3(4, 16, FC1SPLIT), 256>>>(
            out_emb, 2 * E, fc1_w, 2 * E, part, E, Bb, E, FC1KSPL, (size_t)Bb * E,
            nullptr, nullptr, 0);
        fc1_finish_kernel<<<1024, 256>>>(fc1_b);
        // prob = hidden1 @ fc2_w^T + fc2_b
        hmma_gemm<<<dim3(157, 8), 256, HMMA_SMEM>>>(
            h1hi, h1lo, E, f2hi, f2lo, E,
            out_prob, RP1, RP1, E, 0, fc2_b);
        if (i < L - 2) softmax_kernel<<<1024, 256>>>(out_prob);
    }
}

// round 11
// speedup vs baseline: 1.3619x; 1.1138x over previous
#include <cuda_runtime.h>
#include <cuda_bf16.h>
#include <math.h>
#include <stdint.h>

#define Rr   10000
#define E    256
#define Bb   1024
#define L    8
#define RP1  10001
#define KPAD 10240            // padded K for probsf@emb_w
#define NPADW 10112           // fc2_w rows padded (>= 157*64 = 10048)
#define SPLITK 16
#define KSPL 640              // KPAD / SPLITK, mult of 32
#define FC1SPLIT 4
#define FC1KSPL 128

// packed f32x2 helpers (Blackwell FFMA2)
#define PACKF2(d, lo, hi) asm("mov.b64 %0, {%1, %2};" : "=l"(d) : "f"(lo), "f"(hi))
#define FMAF2(acc, a, b)  asm("fma.rn.f32x2 %0, %1, %2, %0;" : "+l"(acc) : "l"(a), "l"(b))
#define UNPACKF2(lo, hi, v) asm("mov.b64 {%0, %1}, %2;" : "=f"(lo), "=f"(hi) : "l"(v))

// ---------------- scratch ----------------
__device__ float g_xT[Bb*L*E];
__device__ __nv_bfloat16 g_xhi[Bb*L*E];
__device__ __nv_bfloat16 g_xlo[Bb*L*E];
__device__ float g_hid[Bb*L*E];
__device__ __nv_bfloat16 g_hhi[Bb*E];
__device__ __nv_bfloat16 g_hlo[Bb*E];
__device__ float g_c[Bb*E];
__device__ float g_gates[Bb*4*E];
__device__ float g_gx[(size_t)Bb*L*4*E];
__device__ __nv_bfloat16 g_h1hi[Bb*E];
__device__ __nv_bfloat16 g_h1lo[Bb*E];
__device__ __nv_bfloat16 g_psfhi[(size_t)Bb*KPAD];
__device__ __nv_bfloat16 g_psflo[(size_t)Bb*KPAD];
__device__ float g_psflast[Bb];
__device__ __nv_bfloat16 g_embThi[(size_t)E*KPAD];
__device__ __nv_bfloat16 g_embTlo[(size_t)E*KPAD];
__device__ __nv_bfloat16 g_fc2whi[(size_t)NPADW*E];
__device__ __nv_bfloat16 g_fc2wlo[(size_t)NPADW*E];
__device__ __nv_bfloat16 g_wihhi[4*E*E];
__device__ __nv_bfloat16 g_wihlo[4*E*E];
__device__ __nv_bfloat16 g_whhhi[4*E*E];
__device__ __nv_bfloat16 g_whhlo[4*E*E];
__device__ float g_biassum[4*E];
__device__ float g_part[SPLITK*Bb*E];

// ---------------- ptx helpers ----------------
__device__ __forceinline__ uint32_t s2u(const void* p) {
    uint32_t a;
    asm("{ .reg .u64 t; cvta.to.shared.u64 t, %1; cvt.u32.u64 %0, t; }" : "=r"(a) : "l"(p));
    return a;
}
__device__ __forceinline__ void ldm4(uint32_t* r, uint32_t addr) {
    asm volatile("ldmatrix.sync.aligned.m8n8.x4.shared.b16 {%0,%1,%2,%3}, [%4];"
                 : "=r"(r[0]), "=r"(r[1]), "=r"(r[2]), "=r"(r[3]) : "r"(addr));
}
__device__ __forceinline__ void mma_bf16(float* d, const uint32_t* a, const uint32_t* b) {
    asm volatile("mma.sync.aligned.m16n8k16.row.col.f32.bf16.bf16.f32 "
                 "{%0,%1,%2,%3}, {%4,%5,%6,%7}, {%8,%9}, {%0,%1,%2,%3};"
                 : "+f"(d[0]), "+f"(d[1]), "+f"(d[2]), "+f"(d[3])
                 : "r"(a[0]), "r"(a[1]), "r"(a[2]), "r"(a[3]), "r"(b[0]), "r"(b[1]));
}
__device__ __forceinline__ void cpa16(uint32_t saddr, const void* gptr) {
    asm volatile("cp.async.cg.shared.global [%0], [%1], 16;" :: "r"(saddr), "l"(gptr) : "memory");
}
#define CP_COMMIT() asm volatile("cp.async.commit_group;" ::: "memory")
#define CP_WAIT1()  asm volatile("cp.async.wait_group 1;" ::: "memory")
#define CP_WAIT0()  asm volatile("cp.async.wait_group 0;" ::: "memory")

__device__ __forceinline__ void split_bf16(float x, __nv_bfloat16& h, __nv_bfloat16& l) {
    h = __float2bfloat16(x);
    l = __float2bfloat16(x - __bfloat162float(h));
}

// ---------------- 128x64-tile double-buffered warp-MMA split-bf16 GEMM ----------------
// 8 warps as 4(M)x2(N); warp tile 32x32. 3 CTAs/SM (60KB smem).
// Epilogue: +bias[n] or +Cin[r*ldc+n].
#define SSTR 40
#define OFF_ALO 10240
#define OFF_BHI 20480
#define OFF_BLO 25600
#define STAGE_B 30720
#define HMMA_SMEM (2*STAGE_B)
__global__ void __launch_bounds__(256)
hmma_gemm(const __nv_bfloat16* __restrict__ Ahi, const __nv_bfloat16* __restrict__ Alo, int lda,
          const __nv_bfloat16* __restrict__ Bhi, const __nv_bfloat16* __restrict__ Blo, int ldb,
          float* __restrict__ C, int ldc, int Nreal, int Klen, size_t zstride,
          const float* __restrict__ bias, const float* __restrict__ Cin)
{
    extern __shared__ char dsm[];
    const uint32_t sb = s2u(dsm);

    const int tid = threadIdx.x, lane = tid & 31, wid = tid >> 5;
    const int bm = blockIdx.y * 128, bn = blockIdx.x * 64;
    const int kbase = blockIdx.z * Klen;
    C += (size_t)blockIdx.z * zstride;
    const int wm = (wid & 3) * 32, wn = (wid >> 2) * 32;

    float acc[2][4][4];
#pragma unroll
    for (int i = 0; i < 2; i++)
#pragma unroll
        for (int j = 0; j < 4; j++)
#pragma unroll
            for (int u = 0; u < 4; u++) acc[i][j][u] = 0.f;

    const int l15 = lane & 15, lq = lane >> 4;
    const int l8 = lane & 7, sel = lane >> 3;
    const int arow0 = tid >> 2, aq0 = tid & 3;
    const int arow1 = arow0 + 64;
    const int brow = tid >> 2, bq = tid & 3;
    const int ntiles = Klen >> 5;

    {
        size_t ga0 = (size_t)(bm + arow0) * lda + kbase + aq0 * 8;
        size_t ga1 = (size_t)(bm + arow1) * lda + kbase + aq0 * 8;
        size_t gb  = (size_t)(bn + brow) * ldb + kbase + bq * 8;
        uint32_t sa0 = sb + (uint32_t)(arow0 * SSTR + aq0 * 8) * 2;
        uint32_t sa1 = sb + (uint32_t)(arow1 * SSTR + aq0 * 8) * 2;
        uint32_t sbb = sb + (uint32_t)(brow * SSTR + bq * 8) * 2;
        cpa16(sa0,           Ahi + ga0); cpa16(sa0 + OFF_ALO, Alo + ga0);
        cpa16(sa1,           Ahi + ga1); cpa16(sa1 + OFF_ALO, Alo + ga1);
        cpa16(sbb + OFF_BHI, Bhi + gb);  cpa16(sbb + OFF_BLO, Blo + gb);
        CP_COMMIT();
    }

    for (int t = 0; t < ntiles; t++) {
        if (t + 1 < ntiles) {
            int kt = kbase + (t + 1) * 32;
            uint32_t stb = sb + ((t + 1) & 1) * STAGE_B;
            size_t ga0 = (size_t)(bm + arow0) * lda + kt + aq0 * 8;
            size_t ga1 = (size_t)(bm + arow1) * lda + kt + aq0 * 8;
            size_t gb  = (size_t)(bn + brow) * ldb + kt + bq * 8;
            uint32_t sa0 = stb + (uint32_t)(arow0 * SSTR + aq0 * 8) * 2;
            uint32_t sa1 = stb + (uint32_t)(arow1 * SSTR + aq0 * 8) * 2;
            uint32_t sbb = stb + (uint32_t)(brow * SSTR + bq * 8) * 2;
            cpa16(sa0,           Ahi + ga0); cpa16(sa0 + OFF_ALO, Alo + ga0);
            cpa16(sa1,           Ahi + ga1); cpa16(sa1 + OFF_ALO, Alo + ga1);
            cpa16(sbb + OFF_BHI, Bhi + gb);  cpa16(sbb + OFF_BLO, Blo + gb);
            CP_COMMIT();
            CP_WAIT1();
        } else {
            CP_WAIT0();
        }
        __syncthreads();

        const uint32_t stb = sb + (t & 1) * STAGE_B;
        const uint32_t aHi = stb, aLo = stb + OFF_ALO, bHi = stb + OFF_BHI, bLo = stb + OFF_BLO;

#pragma unroll
        for (int ks = 0; ks < 2; ks++) {
            uint32_t ahi[2][4], alo[2][4];
#pragma unroll
            for (int mf = 0; mf < 2; mf++) {
                uint32_t off = (uint32_t)((wm + mf * 16 + l15) * SSTR + ks * 16 + lq * 8) * 2;
                ldm4(ahi[mf], aHi + off);
                ldm4(alo[mf], aLo + off);
            }
            uint32_t bhi[4][2], blo[4][2];
#pragma unroll
            for (int p = 0; p < 2; p++) {
                uint32_t off = (uint32_t)((wn + p * 16 + (sel >> 1) * 8 + l8) * SSTR
                                          + ks * 16 + (sel & 1) * 8) * 2;
                uint32_t r[4];
                ldm4(r, bHi + off);
                bhi[p*2][0] = r[0]; bhi[p*2][1] = r[1];
                bhi[p*2+1][0] = r[2]; bhi[p*2+1][1] = r[3];
                ldm4(r, bLo + off);
                blo[p*2][0] = r[0]; blo[p*2][1] = r[1];
                blo[p*2+1][0] = r[2]; blo[p*2+1][1] = r[3];
            }
#pragma unroll
            for (int mf = 0; mf < 2; mf++)
#pragma unroll
                for (int nf = 0; nf < 4; nf++)
                    mma_bf16(acc[mf][nf], ahi[mf], bhi[nf]);
#pragma unroll
            for (int mf = 0; mf < 2; mf++)
#pragma unroll
                for (int nf = 0; nf < 4; nf++)
                    mma_bf16(acc[mf][nf], ahi[mf], blo[nf]);
#pragma unroll
            for (int mf = 0; mf < 2; mf++)
#pragma unroll
                for (int nf = 0; nf < 4; nf++)
                    mma_bf16(acc[mf][nf], alo[mf], bhi[nf]);
        }
        __syncthreads();
    }

    const int crow = lane >> 2, ccol = (lane & 3) * 2;
#pragma unroll
    for (int mf = 0; mf < 2; mf++) {
        int r0 = bm + wm + mf * 16 + crow;
#pragma unroll
        for (int nf = 0; nf < 4; nf++) {
            int c0 = bn + wn + nf * 8 + ccol;
#pragma unroll
            for (int half = 0; half < 2; half++) {
                int r = r0 + half * 8;
#pragma unroll
                for (int u = 0; u < 2; u++) {
                    int n = c0 + u;
                    if (n < Nreal) {
                        float v = acc[mf][nf][half * 2 + u];
                        if (bias) v += bias[n];
                        if (Cin) v += Cin[(size_t)r * ldc + n];
                        C[(size_t)r * ldc + n] = v;
                    }
                }
            }
        }
    }
}

// ---------------- prep / elementwise kernels ----------------
__global__ void prep_bias_kernel(const float* __restrict__ b_ih, const float* __restrict__ b_hh) {
    int idx = blockIdx.x * 256 + threadIdx.x;
    if (idx < 4 * E) g_biassum[idx] = b_ih[idx] + b_hh[idx];
}

__global__ void conv_fc2w_kernel(const float* __restrict__ fc2_w) {
    int idx = blockIdx.x * 256 + threadIdx.x;
    int r = idx >> 8, c = idx & 255;
    float v = (r < RP1) ? fc2_w[r * E + c] : 0.f;
    split_bf16(v, g_fc2whi[idx], g_fc2wlo[idx]);
}

// convert w_ih AND w_hh (each 4E*E = 262144)
__global__ void conv_w_kernel(const float* __restrict__ w_ih, const float* __restrict__ w_hh) {
    int idx = blockIdx.x * 256 + threadIdx.x;
    split_bf16(w_ih[idx], g_wihhi[idx], g_wihlo[idx]);
    split_bf16(w_hh[idx], g_whhhi[idx], g_whhlo[idx]);
}

__global__ void conv_embT_kernel(const float* __restrict__ emb_w) {
    __shared__ float tile[32][33];
    int k0 = blockIdx.x * 32, e0 = blockIdx.y * 32;
    int tx = threadIdx.x & 31, ty = threadIdx.x >> 5;
#pragma unroll
    for (int r = 0; r < 32; r += 8) {
        int k = k0 + ty + r;
        tile[ty + r][tx] = (k < Rr) ? emb_w[(size_t)k * E + e0 + tx] : 0.f;
    }
    __syncthreads();
#pragma unroll
    for (int r = 0; r < 32; r += 8) {
        int e = e0 + ty + r;
        float v = tile[tx][ty + r];
        split_bf16(v, g_embThi[(size_t)e * KPAD + k0 + tx],
                      g_embTlo[(size_t)e * KPAD + k0 + tx]);
    }
}

__global__ void embed_kernel(const int* __restrict__ bodys, const float* __restrict__ emb_w) {
    int idx = blockIdx.x * 256 + threadIdx.x;
    int e = idx & 255, b = (idx >> 8) & 1023, t = idx >> 18;
    float v = emb_w[(size_t)bodys[b * L + t] * E + e];
    g_xT[idx] = v;
    split_bf16(v, g_xhi[idx], g_xlo[idx]);
    if (idx < Bb * E) {
        g_c[idx] = 0.f;
        g_hhi[idx] = __float2bfloat16(0.f);
        g_hlo[idx] = __float2bfloat16(0.f);
    }
}

__device__ __forceinline__ float sigm(float x) { return 1.f / (1.f + __expf(-x)); }

__global__ void lstm_cell_kernel(int t) {
    int idx = blockIdx.x * 256 + threadIdx.x;
    int b = idx >> 8, e = idx & 255;
    const float* g = g_gates + b * (4 * E);
    float gi = g[e], gf = g[E + e], gg = g[2 * E + e], go = g[3 * E + e];
    float cc = sigm(gf) * g_c[idx] + sigm(gi) * tanhf(gg);
    float hh = sigm(go) * tanhf(cc);
    g_c[idx] = cc;
    split_bf16(hh, g_hhi[idx], g_hlo[idx]);
    g_hid[b * (L * E) + t * E + e] = hh;
}

__global__ void concat0_kernel(float* __restrict__ out_emb) {
    int idx = blockIdx.x * 256 + threadIdx.x;
    int b = idx >> 9, j = idx & 511;
    out_emb[idx] = (j < E) ? g_xT[b * E + j] : g_xT[(1024 + b) * E + (j - E)];
}

__global__ void emb1_finish_kernel(float* __restrict__ out_emb,
                                   const float* __restrict__ emb_w, int i) {
    int idx = blockIdx.x * 256 + threadIdx.x;
    int b = idx >> 8, e = idx & 255;
    float s = 0.f;
#pragma unroll
    for (int p = 0; p < SPLITK; p++) s += g_part[p * (Bb * E) + idx];
    s += g_psflast[b] * g_hid[b * (L * E) + i * E + e];
    out_emb[b * (2 * E) + e]     = s;
    out_emb[b * (2 * E) + E + e] = emb_w[(i + 1) * E + e];
}

__global__ void fc1_finish_kernel(const float* __restrict__ fc1_b) {
    int idx = blockIdx.x * 256 + threadIdx.x;
    int e = idx & 255;
    float s = fc1_b[e];
#pragma unroll
    for (int p = 0; p < FC1SPLIT; p++) s += g_part[p * (Bb * E) + idx];
    s = fmaxf(s, 0.f);
    split_bf16(s, g_h1hi[idx], g_h1lo[idx]);
}

// online softmax
__global__ void softmax_kernel(const float* __restrict__ prob) {
    int b = blockIdx.x;
    const float* row = prob + (size_t)b * RP1;
    __nv_bfloat16* ohi = g_psfhi + (size_t)b * KPAD;
    __nv_bfloat16* olo = g_psflo + (size_t)b * KPAD;
    __shared__ float rm[256], rs[256];
    int t = threadIdx.x;
    float m = -1e30f, s = 0.f;
    for (int j = t; j < RP1; j += 256) {
        float x = row[j];
        float mn = fmaxf(m, x);
        s = s * __expf(m - mn) + __expf(x - mn);
        m = mn;
    }
    rm[t] = m; rs[t] = s; __syncthreads();
    for (int st = 128; st > 0; st >>= 1) {
        if (t < st) {
            float m2 = rm[t + st], s2 = rs[t + st];
            float mn = fmaxf(rm[t], m2);
            rs[t] = rs[t] * __expf(rm[t] - mn) + s2 * __expf(m2 - mn);
            rm[t] = mn;
        }
        __syncthreads();
    }
    m = rm[0];
    float inv = 1.f / rs[0];
    for (int j = t; j < KPAD; j += 256) {
        if (j < Rr) {
            float v = __expf(row[j] - m) * inv;
            split_bf16(v, ohi[j], olo[j]);
        } else {
            if (j == Rr) g_psflast[b] = __expf(row[j] - m) * inv;
            ohi[j] = __float2bfloat16(0.f);
            olo[j] = __float2bfloat16(0.f);
        }
    }
}

// ---------------- 64x64 FFMA2 GEMM (fc1 split-K) ----------------
#define BMT 64
#define BNT 64
#define BKT 16
template<bool TRANSB>
__global__ void gemm_kernel(const float* __restrict__ A, int lda,
                            const float* __restrict__ B, int ldb,
                            float* __restrict__ C, int ldc,
                            int M, int N, int Klen, size_t zstride)
{
    __shared__ float As[BKT][BMT + 4];
    __shared__ float Bs[BKT][BNT + 4];
    int bm = blockIdx.y * BMT, bn = blockIdx.x * BNT;
    int kbase = blockIdx.z * Klen;
    C += (size_t)blockIdx.z * zstride;
    int tid = threadIdx.x;
    int tx = tid & 15, ty = tid >> 4;
    unsigned long long acc[4][2];
#pragma unroll
    for (int i = 0; i < 4; i++) { acc[i][0] = 0ULL; acc[i][1] = 0ULL; }

    for (int kt = 0; kt < Klen; kt += BKT) {
#pragma unroll
        for (int j = 0; j < 4; j++) {
            int idx = tid + j * 256;
            int m = idx >> 4, k = idx & 15;
            As[k][m] = A[(size_t)(bm + m) * lda + kbase + kt + k];
        }
#pragma unroll
        for (int j = 0; j < 4; j++) {
            int idx = tid + j * 256;
            if (TRANSB) {
                int n = idx >> 4, k = idx & 15;
                Bs[k][n] = (bn + n < N) ? B[(size_t)(bn + n) * ldb + kbase + kt + k] : 0.f;
            } else {
                int k = idx >> 6, n = idx & 63;
                Bs[k][n] = (bn + n < N) ? B[(size_t)(kbase + kt + k) * ldb + bn + n] : 0.f;
            }
        }
        __syncthreads();
#pragma unroll
        for (int kk = 0; kk < BKT; kk++) {
            float4 a4 = *(const float4*)&As[kk][ty * 4];
            float4 b4 = *(const float4*)&Bs[kk][tx * 4];
            unsigned long long bp0, bp1;
            PACKF2(bp0, b4.x, b4.y); PACKF2(bp1, b4.z, b4.w);
            float av[4] = {a4.x, a4.y, a4.z, a4.w};
#pragma unroll
            for (int i = 0; i < 4; i++) {
                unsigned long long a2;
                PACKF2(a2, av[i], av[i]);
                FMAF2(acc[i][0], a2, bp0);
                FMAF2(acc[i][1], a2, bp1);
            }
        }
        __syncthreads();
    }
#pragma unroll
    for (int i = 0; i < 4; i++) {
        int m = bm + ty * 4 + i;
#pragma unroll
        for (int j = 0; j < 2; j++) {
            int nbase = bn + tx * 4 + 2 * j;
            float lo, hi;
            UNPACKF2(lo, hi, acc[i][j]);
            if (nbase < N)     C[(size_t)m * ldc + nbase]     = lo;
            if (nbase + 1 < N) C[(size_t)m * ldc + nbase + 1] = hi;
        }
    }
}

// ---------------- launch ----------------
extern "C" void kernel_launch(void* const* d_in, const int* in_sizes, int n_in,
                              void* d_out, int out_size) {
    const int*   bodys = (const int*)  d_in[0];
    const float* emb_w = (const float*)d_in[1];
    const float* w_ih  = (const float*)d_in[2];
    const float* w_hh  = (const float*)d_in[3];
    const float* b_ih  = (const float*)d_in[4];
    const float* b_hh  = (const float*)d_in[5];
    const float* fc1_w = (const float*)d_in[6];
    const float* fc1_b = (const float*)d_in[7];
    const float* fc2_w = (const float*)d_in[8];
    const float* fc2_b = (const float*)d_in[9];

    float* out_prob = (float*)d_out;
    float* out_emb  = out_prob + (size_t)Bb * RP1;

    cudaFuncSetAttribute(hmma_gemm, cudaFuncAttributeMaxDynamicSharedMemorySize, HMMA_SMEM);

    float *biassum, *part, *gx, *gates;
    __nv_bfloat16 *xhi, *xlo, *hhi, *hlo, *h1hi, *h1lo, *psfhi, *psflo;
    __nv_bfloat16 *eThi, *eTlo, *f2hi, *f2lo, *wihhi, *wihlo, *whhhi, *whhlo;
    cudaGetSymbolAddress((void**)&biassum, g_biassum);
    cudaGetSymbolAddress((void**)&part,    g_part);
    cudaGetSymbolAddress((void**)&gx,      g_gx);
    cudaGetSymbolAddress((void**)&gates,   g_gates);
    cudaGetSymbolAddress((void**)&xhi,     g_xhi);
    cudaGetSymbolAddress((void**)&xlo,     g_xlo);
    cudaGetSymbolAddress((void**)&hhi,     g_hhi);
    cudaGetSymbolAddress((void**)&hlo,     g_hlo);
    cudaGetSymbolAddress((void**)&h1hi,    g_h1hi);
    cudaGetSymbolAddress((void**)&h1lo,    g_h1lo);
    cudaGetSymbolAddress((void**)&psfhi,   g_psfhi);
    cudaGetSymbolAddress((void**)&psflo,   g_psflo);
    cudaGetSymbolAddress((void**)&eThi,    g_embThi);
    cudaGetSymbolAddress((void**)&eTlo,    g_embTlo);
    cudaGetSymbolAddress((void**)&f2hi,    g_fc2whi);
    cudaGetSymbolAddress((void**)&f2lo,    g_fc2wlo);
    cudaGetSymbolAddress((void**)&wihhi,   g_wihhi);
    cudaGetSymbolAddress((void**)&wihlo,   g_wihlo);
    cudaGetSymbolAddress((void**)&whhhi,   g_whhhi);
    cudaGetSymbolAddress((void**)&whhlo,   g_whhlo);

    // slot-4 = gx HMMA (profiler capture)
    prep_bias_kernel<<<4, 256>>>(b_ih, b_hh);
    conv_w_kernel<<<(4 * E * E) / 256, 256>>>(w_ih, w_hh);
    embed_kernel<<<8192, 256>>>(bodys, emb_w);
    hmma_gemm<<<dim3(16, 64), 256, HMMA_SMEM>>>(
        xhi, xlo, E, wihhi, wihlo, E,
        gx, 4 * E, 4 * E, E, 0, biassum, nullptr);
    conv_fc2w_kernel<<<(NPADW * E) / 256, 256>>>(fc2_w);
    conv_embT_kernel<<<dim3(KPAD / 32, E / 32), 256>>>(emb_w);

    // LSTM steps: gates = h @ w_hh^T + gx_t : pipelined HMMA (128 CTAs) + cell
    for (int t = 0; t < L; t++) {
        hmma_gemm<<<dim3(16, 8), 256, HMMA_SMEM>>>(
            hhi, hlo, E, whhhi, whhlo, E,
            gates, 4 * E, 4 * E, E, 0,
            nullptr, gx + (size_t)t * Bb * 4 * E);
        lstm_cell_kernel<<<1024, 256>>>(t);
    }

    for (int i = 0; i < L - 1; i++) {
        if (i == 0) {
            concat0_kernel<<<2048, 256>>>(out_emb);
        } else {
            // emb_1 = prob_sf[:, :R] @ emb_w : HMMA split-K x16 (512 CTAs)
            hmma_gemm<<<dim3(4, 8, SPLITK), 256, HMMA_SMEM>>>(
                psfhi, psflo, KPAD, eThi, eTlo, KPAD,
                part, E, E, KSPL, (size_t)Bb * E, nullptr, nullptr);
            emb1_finish_kernel<<<1024, 256>>>(out_emb, emb_w, i);
        }
        // fc1: split-K x4 partials + finish
        gemm_kernel<true><<<dim3(4, 16, FC1SPLIT), 256>>>(
            out_emb, 2 * E, fc1_w, 2 * E, part, E, Bb, E, FC1KSPL, (size_t)Bb * E);
        fc1_finish_kernel<<<1024, 256>>>(fc1_b);
        // prob = hidden1 @ fc2_w^T + fc2_b
        hmma_gemm<<<dim3(157, 8), 256, HMMA_SMEM>>>(
            h1hi, h1lo, E, f2hi, f2lo, E,
            out_prob, RP1, RP1, E, 0, fc2_b, nullptr);
        if (i < L - 2) softmax_kernel<<<1024, 256>>>(out_prob);
    }
}